// round 1
// baseline (speedup 1.0000x reference)
#include <cuda_runtime.h>
#include <cuda_bf16.h>
#include <math.h>

// Problem constants
#define Bb 2
#define Tt 2048
#define Cc 1024
#define NH 16
#define HD 64
#define MROWS (Bb*Tt)          // 4096
#define QKV_N (3*Cc)           // 3072

// Scratch (static __device__ arrays; no allocation allowed)
__device__ float g_xn [MROWS*Cc];          // LN output        [4096,1024]
__device__ float g_q  [Bb*NH*Tt*HD];       // [b,h,t,d]
__device__ float g_k  [Bb*NH*Tt*HD];
__device__ float g_v  [Bb*NH*Tt*HD];
__device__ float g_att[MROWS*Cc];          // attention out    [b,t,h*64+d]

// ---------------------------------------------------------------------------
// LayerNorm: one block per row (C=1024), 256 threads, float4 per thread.
// ---------------------------------------------------------------------------
__device__ __forceinline__ float block_sum256(float v, float* red) {
    #pragma unroll
    for (int o = 16; o > 0; o >>= 1) v += __shfl_xor_sync(0xffffffffu, v, o);
    int w = threadIdx.x >> 5;
    if ((threadIdx.x & 31) == 0) red[w] = v;
    __syncthreads();
    float t = (threadIdx.x < 8) ? red[threadIdx.x] : 0.f;
    if (threadIdx.x < 32) {
        #pragma unroll
        for (int o = 4; o > 0; o >>= 1) t += __shfl_xor_sync(0xffffffffu, t, o);
        if (threadIdx.x == 0) red[0] = t;
    }
    __syncthreads();
    float r = red[0];
    __syncthreads();
    return r;
}

__global__ __launch_bounds__(256) void ln_kernel(
    const float* __restrict__ x, const float* __restrict__ scale,
    const float* __restrict__ bias) {
    __shared__ float red[8];
    const int row = blockIdx.x;
    const int tid = threadIdx.x;
    float4 v = reinterpret_cast<const float4*>(x + (size_t)row * Cc)[tid];
    float s = v.x + v.y + v.z + v.w;
    float mu = block_sum256(s, red) * (1.f / Cc);
    float dx = v.x - mu, dy = v.y - mu, dz = v.z - mu, dw = v.w - mu;
    float sq = dx*dx + dy*dy + dz*dz + dw*dw;
    float var = block_sum256(sq, red) * (1.f / Cc);
    float inv = rsqrtf(var + 1e-6f);
    float4 sc = reinterpret_cast<const float4*>(scale)[tid];
    float4 bi = reinterpret_cast<const float4*>(bias)[tid];
    float4 o;
    o.x = dx * inv * sc.x + bi.x;
    o.y = dy * inv * sc.y + bi.y;
    o.z = dz * inv * sc.z + bi.z;
    o.w = dw * inv * sc.w + bi.w;
    reinterpret_cast<float4*>(g_xn + (size_t)row * Cc)[tid] = o;
}

// ---------------------------------------------------------------------------
// SGEMM 128x128 block tile, 8x8 microtile, BK=8, 256 threads.
// Two instantiations differing only in N-dim and epilogue.
// ---------------------------------------------------------------------------
__global__ __launch_bounds__(256) void gemm_qkv_kernel(
    const float* __restrict__ Bw, const float* __restrict__ bias) {
    constexpr int Kd = Cc, Nd = QKV_N;
    __shared__ float As[8][128];
    __shared__ float Bs[8][128];
    const int tid  = threadIdx.x;
    const int trow = tid >> 4;          // 0..15
    const int tcol = tid & 15;          // 0..15
    const int arow = tid >> 1;          // 0..127
    const int acol = (tid & 1) << 2;    // 0 or 4
    const int brow = tid >> 5;          // 0..7
    const int bcol = (tid & 31) << 2;   // 0..124
    const float* Ap = g_xn + (size_t)blockIdx.y * 128 * Kd;
    const float* Bp = Bw + (size_t)blockIdx.x * 128;

    float res[8][8];
    #pragma unroll
    for (int i = 0; i < 8; i++)
        #pragma unroll
        for (int j = 0; j < 8; j++) res[i][j] = 0.f;

    for (int k0 = 0; k0 < Kd; k0 += 8) {
        float4 a = *reinterpret_cast<const float4*>(Ap + (size_t)arow * Kd + k0 + acol);
        As[acol+0][arow] = a.x; As[acol+1][arow] = a.y;
        As[acol+2][arow] = a.z; As[acol+3][arow] = a.w;
        *reinterpret_cast<float4*>(&Bs[brow][bcol]) =
            *reinterpret_cast<const float4*>(Bp + (size_t)(k0 + brow) * Nd + bcol);
        __syncthreads();
        #pragma unroll
        for (int kk = 0; kk < 8; kk++) {
            float4 a0 = *reinterpret_cast<const float4*>(&As[kk][trow*8]);
            float4 a1 = *reinterpret_cast<const float4*>(&As[kk][trow*8+4]);
            float4 b0 = *reinterpret_cast<const float4*>(&Bs[kk][tcol*8]);
            float4 b1 = *reinterpret_cast<const float4*>(&Bs[kk][tcol*8+4]);
            float am[8] = {a0.x,a0.y,a0.z,a0.w,a1.x,a1.y,a1.z,a1.w};
            float bn[8] = {b0.x,b0.y,b0.z,b0.w,b1.x,b1.y,b1.z,b1.w};
            #pragma unroll
            for (int i = 0; i < 8; i++)
                #pragma unroll
                for (int j = 0; j < 8; j++)
                    res[i][j] = fmaf(am[i], bn[j], res[i][j]);
        }
        __syncthreads();
    }
    // Epilogue: scatter into Q/K/V [b,h,t,d]; q pre-scaled by 1/8
    #pragma unroll
    for (int i = 0; i < 8; i++) {
        int m = blockIdx.y * 128 + trow * 8 + i;
        int b = m >> 11, t = m & 2047;
        #pragma unroll
        for (int j = 0; j < 8; j++) {
            int n = blockIdx.x * 128 + tcol * 8 + j;
            float val = res[i][j] + bias[n];
            int which = n >> 10;
            int r = n & 1023;
            int h = r >> 6, d = r & 63;
            int idx = (((b * NH + h) * Tt) + t) * HD + d;
            if (which == 0)      g_q[idx] = val * 0.125f;
            else if (which == 1) g_k[idx] = val;
            else                 g_v[idx] = val;
        }
    }
}

__global__ __launch_bounds__(256) void gemm_proj_kernel(
    const float* __restrict__ Bw, const float* __restrict__ bias,
    float* __restrict__ Cout) {
    constexpr int Kd = Cc, Nd = Cc;
    __shared__ float As[8][128];
    __shared__ float Bs[8][128];
    const int tid  = threadIdx.x;
    const int trow = tid >> 4;
    const int tcol = tid & 15;
    const int arow = tid >> 1;
    const int acol = (tid & 1) << 2;
    const int brow = tid >> 5;
    const int bcol = (tid & 31) << 2;
    const float* Ap = g_att + (size_t)blockIdx.y * 128 * Kd;
    const float* Bp = Bw + (size_t)blockIdx.x * 128;

    float res[8][8];
    #pragma unroll
    for (int i = 0; i < 8; i++)
        #pragma unroll
        for (int j = 0; j < 8; j++) res[i][j] = 0.f;

    for (int k0 = 0; k0 < Kd; k0 += 8) {
        float4 a = *reinterpret_cast<const float4*>(Ap + (size_t)arow * Kd + k0 + acol);
        As[acol+0][arow] = a.x; As[acol+1][arow] = a.y;
        As[acol+2][arow] = a.z; As[acol+3][arow] = a.w;
        *reinterpret_cast<float4*>(&Bs[brow][bcol]) =
            *reinterpret_cast<const float4*>(Bp + (size_t)(k0 + brow) * Nd + bcol);
        __syncthreads();
        #pragma unroll
        for (int kk = 0; kk < 8; kk++) {
            float4 a0 = *reinterpret_cast<const float4*>(&As[kk][trow*8]);
            float4 a1 = *reinterpret_cast<const float4*>(&As[kk][trow*8+4]);
            float4 b0 = *reinterpret_cast<const float4*>(&Bs[kk][tcol*8]);
            float4 b1 = *reinterpret_cast<const float4*>(&Bs[kk][tcol*8+4]);
            float am[8] = {a0.x,a0.y,a0.z,a0.w,a1.x,a1.y,a1.z,a1.w};
            float bn[8] = {b0.x,b0.y,b0.z,b0.w,b1.x,b1.y,b1.z,b1.w};
            #pragma unroll
            for (int i = 0; i < 8; i++)
                #pragma unroll
                for (int j = 0; j < 8; j++)
                    res[i][j] = fmaf(am[i], bn[j], res[i][j]);
        }
        __syncthreads();
    }
    #pragma unroll
    for (int i = 0; i < 8; i++) {
        int m = blockIdx.y * 128 + trow * 8 + i;
        #pragma unroll
        for (int j = 0; j < 8; j++) {
            int n = blockIdx.x * 128 + tcol * 8 + j;
            Cout[(size_t)m * Nd + n] = res[i][j] + bias[n];
        }
    }
}

// ---------------------------------------------------------------------------
// Fused causal flash attention (fp32): BQ=64, BK=64, D=64, 256 threads.
// grid = (T/64, B*H). Online softmax; only lower-triangle KV tiles visited.
// ---------------------------------------------------------------------------
#define PAD 65
__global__ __launch_bounds__(256) void flash_kernel() {
    extern __shared__ float sm[];
    float* Qs   = sm;                  // 64*65
    float* Ks   = Qs + 64 * PAD;
    float* Vs   = Ks + 64 * PAD;
    float* Ss   = Vs + 64 * PAD;
    float* rowM = Ss + 64 * PAD;
    float* rowL = rowM + 64;
    float* rowA = rowL + 64;

    const int tid = threadIdx.x;
    const int qb = blockIdx.x, bh = blockIdx.y;
    const int q0 = qb * 64;
    const float* Qh = g_q + (size_t)bh * Tt * HD;
    const float* Kh = g_k + (size_t)bh * Tt * HD;
    const float* Vh = g_v + (size_t)bh * Tt * HD;

    #pragma unroll
    for (int u = 0; u < 16; u++) {
        int idx = u * 256 + tid;
        int r = idx >> 6, c = idx & 63;
        Qs[r * PAD + c] = Qh[(size_t)(q0 + r) * HD + c];
    }
    if (tid < 64) { rowM[tid] = -1e30f; rowL[tid] = 0.f; }

    const int ty = tid >> 4, tx = tid & 15;
    float o[4][4] = {};
    __syncthreads();

    for (int kt = 0; kt <= qb; kt++) {
        const int k0 = kt * 64;
        #pragma unroll
        for (int u = 0; u < 16; u++) {
            int idx = u * 256 + tid;
            int r = idx >> 6, c = idx & 63;
            Ks[r * PAD + c] = Kh[(size_t)(k0 + r) * HD + c];
            Vs[r * PAD + c] = Vh[(size_t)(k0 + r) * HD + c];
        }
        __syncthreads();

        // S = Q K^T  (64x64 tile, 4x4 per thread)
        float s[4][4] = {};
        #pragma unroll 4
        for (int d = 0; d < 64; d++) {
            float qv[4], kv[4];
            #pragma unroll
            for (int i = 0; i < 4; i++) qv[i] = Qs[(ty*4+i)*PAD + d];
            #pragma unroll
            for (int j = 0; j < 4; j++) kv[j] = Ks[(tx*4+j)*PAD + d];
            #pragma unroll
            for (int i = 0; i < 4; i++)
                #pragma unroll
                for (int j = 0; j < 4; j++)
                    s[i][j] = fmaf(qv[i], kv[j], s[i][j]);
        }
        if (kt == qb) {
            #pragma unroll
            for (int i = 0; i < 4; i++)
                #pragma unroll
                for (int j = 0; j < 4; j++)
                    if (k0 + tx*4+j > q0 + ty*4+i) s[i][j] = -1e30f;
        }
        #pragma unroll
        for (int i = 0; i < 4; i++)
            #pragma unroll
            for (int j = 0; j < 4; j++)
                Ss[(ty*4+i)*PAD + tx*4+j] = s[i][j];
        __syncthreads();

        // Online softmax: 4 threads per row (same warp, lanes aligned)
        {
            int r = tid >> 2, seg = tid & 3;
            float* srow = Ss + r * PAD + seg * 16;
            float mx = -1e30f;
            #pragma unroll
            for (int c = 0; c < 16; c++) mx = fmaxf(mx, srow[c]);
            mx = fmaxf(mx, __shfl_xor_sync(0xffffffffu, mx, 1));
            mx = fmaxf(mx, __shfl_xor_sync(0xffffffffu, mx, 2));
            float mo = rowM[r];
            float mn = fmaxf(mo, mx);
            float al = __expf(mo - mn);
            float ssum = 0.f;
            #pragma unroll
            for (int c = 0; c < 16; c++) {
                float p = __expf(srow[c] - mn);
                srow[c] = p;
                ssum += p;
            }
            ssum += __shfl_xor_sync(0xffffffffu, ssum, 1);
            ssum += __shfl_xor_sync(0xffffffffu, ssum, 2);
            if (seg == 0) {
                rowM[r] = mn;
                rowL[r] = rowL[r] * al + ssum;
                rowA[r] = al;
            }
        }
        __syncthreads();

        // rescale O, accumulate O += P V
        float al[4];
        #pragma unroll
        for (int i = 0; i < 4; i++) al[i] = rowA[ty*4+i];
        #pragma unroll
        for (int i = 0; i < 4; i++)
            #pragma unroll
            for (int j = 0; j < 4; j++) o[i][j] *= al[i];
        #pragma unroll 4
        for (int kk = 0; kk < 64; kk++) {
            float p[4], v[4];
            #pragma unroll
            for (int i = 0; i < 4; i++) p[i] = Ss[(ty*4+i)*PAD + kk];
            #pragma unroll
            for (int j = 0; j < 4; j++) v[j] = Vs[kk*PAD + tx*4+j];
            #pragma unroll
            for (int i = 0; i < 4; i++)
                #pragma unroll
                for (int j = 0; j < 4; j++)
                    o[i][j] = fmaf(p[i], v[j], o[i][j]);
        }
        __syncthreads();
    }

    const int b = bh >> 4, h = bh & 15;
    #pragma unroll
    for (int i = 0; i < 4; i++) {
        float inv = 1.f / rowL[ty*4+i];
        int t = q0 + ty*4+i;
        #pragma unroll
        for (int j = 0; j < 4; j++)
            g_att[((size_t)(b * Tt + t)) * Cc + h * HD + tx*4+j] = o[i][j] * inv;
    }
}

// ---------------------------------------------------------------------------
extern "C" void kernel_launch(void* const* d_in, const int* in_sizes, int n_in,
                              void* d_out, int out_size) {
    const float* x        = (const float*)d_in[0];
    // d_in[1] = mask (causal, known statically — unused)
    const float* ln_scale = (const float*)d_in[2];
    const float* ln_bias  = (const float*)d_in[3];
    const float* qkv_w    = (const float*)d_in[4];
    const float* qkv_b    = (const float*)d_in[5];
    const float* proj_w   = (const float*)d_in[6];
    const float* proj_b   = (const float*)d_in[7];
    float* out = (float*)d_out;

    static bool attr_set = false;
    if (!attr_set) {
        cudaFuncSetAttribute(flash_kernel,
                             cudaFuncAttributeMaxDynamicSharedMemorySize,
                             (4 * 64 * PAD + 3 * 64) * (int)sizeof(float));
        attr_set = true;
    }

    ln_kernel<<<MROWS, 256>>>(x, ln_scale, ln_bias);
    gemm_qkv_kernel<<<dim3(QKV_N / 128, MROWS / 128), 256>>>(qkv_w, qkv_b);
    flash_kernel<<<dim3(Tt / 64, Bb * NH), 256,
                   (4 * 64 * PAD + 3 * 64) * (int)sizeof(float)>>>();
    gemm_proj_kernel<<<dim3(Cc / 128, MROWS / 128), 256>>>(proj_w, proj_b, out);
}

// round 4
// speedup vs baseline: 1.4673x; 1.4673x over previous
#include <cuda_runtime.h>
#include <cuda_bf16.h>
#include <cstdint>
#include <math.h>

#define Bb 2
#define Tt 2048
#define Cc 1024
#define NH 16
#define HD 64
#define MROWS (Bb*Tt)          // 4096
#define QKV_N (3*Cc)           // 3072

// Scratch
__device__ __nv_bfloat16 g_xnh [MROWS*Cc];
__device__ __nv_bfloat16 g_xnl [MROWS*Cc];
__device__ __nv_bfloat16 g_wqh [Cc*QKV_N];
__device__ __nv_bfloat16 g_wql [Cc*QKV_N];
__device__ __nv_bfloat16 g_wph [Cc*Cc];
__device__ __nv_bfloat16 g_wpl [Cc*Cc];
__device__ float g_q  [Bb*NH*Tt*HD];       // [b,h,t,d]
__device__ float g_k  [Bb*NH*Tt*HD];
__device__ float g_v  [Bb*NH*Tt*HD];
__device__ __nv_bfloat16 g_atth[MROWS*Cc];
__device__ __nv_bfloat16 g_attl[MROWS*Cc];

__device__ __forceinline__ uint32_t smem_u32(const void* p) {
    return (uint32_t)__cvta_generic_to_shared(p);
}
__device__ __forceinline__ void cp16(uint32_t dst, const void* src) {
    asm volatile("cp.async.ca.shared.global [%0], [%1], 16;\n" :: "r"(dst), "l"(src));
}
__device__ __forceinline__ void cp_commit() { asm volatile("cp.async.commit_group;\n"); }
template<int N> __device__ __forceinline__ void cp_wait() {
    asm volatile("cp.async.wait_group %0;\n" :: "n"(N));
}
__device__ __forceinline__ void ldsm_x4(uint32_t a[4], uint32_t addr) {
    asm volatile("ldmatrix.sync.aligned.m8n8.x4.shared.b16 {%0,%1,%2,%3}, [%4];"
                 : "=r"(a[0]),"=r"(a[1]),"=r"(a[2]),"=r"(a[3]) : "r"(addr));
}
__device__ __forceinline__ void ldsm_x2t(uint32_t b[2], uint32_t addr) {
    asm volatile("ldmatrix.sync.aligned.m8n8.x2.trans.shared.b16 {%0,%1}, [%2];"
                 : "=r"(b[0]),"=r"(b[1]) : "r"(addr));
}
__device__ __forceinline__ void mma_bf16(float c[4], const uint32_t a[4], const uint32_t b[2]) {
    asm volatile("mma.sync.aligned.m16n8k16.row.col.f32.bf16.bf16.f32 "
        "{%0,%1,%2,%3}, {%4,%5,%6,%7}, {%8,%9}, {%0,%1,%2,%3};"
        : "+f"(c[0]),"+f"(c[1]),"+f"(c[2]),"+f"(c[3])
        : "r"(a[0]),"r"(a[1]),"r"(a[2]),"r"(a[3]), "r"(b[0]),"r"(b[1]));
}
__device__ __forceinline__ void split_bf16(float v, __nv_bfloat16& h, __nv_bfloat16& l) {
    h = __float2bfloat16(v);
    l = __float2bfloat16(v - __bfloat162float(h));
}

// ---------------------------------------------------------------------------
// LayerNorm -> bf16 hi/lo
// ---------------------------------------------------------------------------
__device__ __forceinline__ float block_sum256(float v, float* red) {
    #pragma unroll
    for (int o = 16; o > 0; o >>= 1) v += __shfl_xor_sync(0xffffffffu, v, o);
    int w = threadIdx.x >> 5;
    if ((threadIdx.x & 31) == 0) red[w] = v;
    __syncthreads();
    float t = (threadIdx.x < 8) ? red[threadIdx.x] : 0.f;
    if (threadIdx.x < 32) {
        #pragma unroll
        for (int o = 4; o > 0; o >>= 1) t += __shfl_xor_sync(0xffffffffu, t, o);
        if (threadIdx.x == 0) red[0] = t;
    }
    __syncthreads();
    float r = red[0];
    __syncthreads();
    return r;
}

__global__ __launch_bounds__(256) void ln_kernel(
    const float* __restrict__ x, const float* __restrict__ scale,
    const float* __restrict__ bias) {
    __shared__ float red[8];
    const int row = blockIdx.x;
    const int tid = threadIdx.x;
    float4 v = reinterpret_cast<const float4*>(x + (size_t)row * Cc)[tid];
    float s = v.x + v.y + v.z + v.w;
    float mu = block_sum256(s, red) * (1.f / Cc);
    float dx = v.x - mu, dy = v.y - mu, dz = v.z - mu, dw = v.w - mu;
    float sq = dx*dx + dy*dy + dz*dz + dw*dw;
    float var = block_sum256(sq, red) * (1.f / Cc);
    float inv = rsqrtf(var + 1e-6f);
    float4 sc = reinterpret_cast<const float4*>(scale)[tid];
    float4 bi = reinterpret_cast<const float4*>(bias)[tid];
    float o[4];
    o[0] = dx * inv * sc.x + bi.x;
    o[1] = dy * inv * sc.y + bi.y;
    o[2] = dz * inv * sc.z + bi.z;
    o[3] = dw * inv * sc.w + bi.w;
    size_t base = (size_t)row * Cc + tid * 4;
    #pragma unroll
    for (int e = 0; e < 4; e++) {
        __nv_bfloat16 h, l;
        split_bf16(o[e], h, l);
        g_xnh[base + e] = h;
        g_xnl[base + e] = l;
    }
}

// ---------------------------------------------------------------------------
// fp32 -> bf16 hi/lo conversion (weights)
// ---------------------------------------------------------------------------
__global__ __launch_bounds__(256) void cvt_kernel(
    const float* __restrict__ src, __nv_bfloat16* __restrict__ hi,
    __nv_bfloat16* __restrict__ lo) {
    int i = (blockIdx.x * 256 + threadIdx.x) * 4;
    float4 v = *reinterpret_cast<const float4*>(src + i);
    float a[4] = {v.x, v.y, v.z, v.w};
    #pragma unroll
    for (int e = 0; e < 4; e++) {
        __nv_bfloat16 h, l;
        split_bf16(a[e], h, l);
        hi[i + e] = h;
        lo[i + e] = l;
    }
}

// ---------------------------------------------------------------------------
// bf16x3 tensor-core GEMM: 128x128 block, 8 warps (2x4), warp tile 64x32.
// C = Ah*Bh + Ah*Bl + Al*Bh, fp32 accum. K-chunk 32, cp.async double-buffer.
// ---------------------------------------------------------------------------
#define STAGE_E 18944
#define A_STR 40
#define B_STR 136

template<int ND, int EPI>
__global__ __launch_bounds__(256) void mma_gemm(
    const __nv_bfloat16* __restrict__ Ah_g, const __nv_bfloat16* __restrict__ Al_g,
    const __nv_bfloat16* __restrict__ Bh_g, const __nv_bfloat16* __restrict__ Bl_g,
    const float* __restrict__ bias, float* __restrict__ Cout)
{
    extern __shared__ __nv_bfloat16 smem[];
    const int tid = threadIdx.x;
    const int wid = tid >> 5, lane = tid & 31;
    const int wm = wid >> 2, wn = wid & 3;
    const int row0 = blockIdx.y * 128;
    const int col0 = blockIdx.x * 128;

    const int laneRowA = (lane & 7) + ((lane >> 3) & 1) * 8;
    const int laneColA = (lane >> 4) * 8;
    const int laneB = lane & 15;

    auto issue = [&](int it, int stage) {
        const int k0 = it * 32;
        __nv_bfloat16* s = smem + stage * STAGE_E;
        #pragma unroll
        for (int u = 0; u < 2; u++) {
            int c = tid + u * 256;
            int ar = c >> 2, ac = (c & 3) * 8;
            cp16(smem_u32(s + ar * A_STR + ac),
                 Ah_g + (size_t)(row0 + ar) * Cc + k0 + ac);
            cp16(smem_u32(s + 5120 + ar * A_STR + ac),
                 Al_g + (size_t)(row0 + ar) * Cc + k0 + ac);
            int br = c >> 4, bc = (c & 15) * 8;
            cp16(smem_u32(s + 10240 + br * B_STR + bc),
                 Bh_g + (size_t)(k0 + br) * ND + col0 + bc);
            cp16(smem_u32(s + 14592 + br * B_STR + bc),
                 Bl_g + (size_t)(k0 + br) * ND + col0 + bc);
        }
        cp_commit();
    };

    float acc[4][4][4] = {};
    issue(0, 0);

    #pragma unroll 1
    for (int it = 0; it < 32; it++) {
        const int buf = it & 1;
        if (it + 1 < 32) { issue(it + 1, buf ^ 1); cp_wait<1>(); }
        else             { cp_wait<0>(); }
        __syncthreads();
        __nv_bfloat16* sAh = smem + buf * STAGE_E;
        __nv_bfloat16* sAl = sAh + 5120;
        __nv_bfloat16* sBh = sAh + 10240;
        __nv_bfloat16* sBl = sAh + 14592;
        #pragma unroll
        for (int kk = 0; kk < 2; kk++) {
            uint32_t ah[4][4], al[4][4], bh[4][2], bl[4][2];
            #pragma unroll
            for (int i = 0; i < 4; i++) {
                int r = wm * 64 + i * 16 + laneRowA;
                int cA = kk * 16 + laneColA;
                ldsm_x4(ah[i], smem_u32(sAh + r * A_STR + cA));
                ldsm_x4(al[i], smem_u32(sAl + r * A_STR + cA));
            }
            #pragma unroll
            for (int j = 0; j < 4; j++) {
                int rB = kk * 16 + laneB;
                int cB = wn * 32 + j * 8;
                ldsm_x2t(bh[j], smem_u32(sBh + rB * B_STR + cB));
                ldsm_x2t(bl[j], smem_u32(sBl + rB * B_STR + cB));
            }
            #pragma unroll
            for (int i = 0; i < 4; i++)
                #pragma unroll
                for (int j = 0; j < 4; j++) {
                    mma_bf16(acc[i][j], ah[i], bh[j]);
                    mma_bf16(acc[i][j], ah[i], bl[j]);
                    mma_bf16(acc[i][j], al[i], bh[j]);
                }
        }
        __syncthreads();
    }

    // Epilogue
    #pragma unroll
    for (int i = 0; i < 4; i++) {
        int rbase = row0 + wm * 64 + i * 16 + (lane >> 2);
        #pragma unroll
        for (int j = 0; j < 4; j++) {
            int nb = col0 + wn * 32 + j * 8 + (lane & 3) * 2;
            #pragma unroll
            for (int e = 0; e < 4; e++) {
                int m = rbase + (e >> 1) * 8;
                int n = nb + (e & 1);
                float val = acc[i][j][e] + bias[n];
                if (EPI == 1) {
                    Cout[(size_t)m * Cc + n] = val;
                } else {
                    int b = m >> 11, t = m & 2047;
                    int which = n >> 10, rr = n & 1023;
                    int h = rr >> 6, d = rr & 63;
                    int idx = (((b * NH + h) * Tt) + t) * HD + d;
                    if (which == 0)      g_q[idx] = val * 0.125f;
                    else if (which == 1) g_k[idx] = val;
                    else                 g_v[idx] = val;
                }
            }
        }
    }
}

// ---------------------------------------------------------------------------
// Fused causal flash attention (fp32): BQ=64, BK=64, D=64, 256 threads.
// ---------------------------------------------------------------------------
#define PAD 65
__global__ __launch_bounds__(256) void flash_kernel() {
    extern __shared__ float sm[];
    float* Qs   = sm;
    float* Ks   = Qs + 64 * PAD;
    float* Vs   = Ks + 64 * PAD;
    float* Ss   = Vs + 64 * PAD;
    float* rowM = Ss + 64 * PAD;
    float* rowL = rowM + 64;
    float* rowA = rowL + 64;

    const int tid = threadIdx.x;
    const int qb = blockIdx.x, bh = blockIdx.y;
    const int q0 = qb * 64;
    const float* Qh = g_q + (size_t)bh * Tt * HD;
    const float* Kh = g_k + (size_t)bh * Tt * HD;
    const float* Vh = g_v + (size_t)bh * Tt * HD;

    #pragma unroll
    for (int u = 0; u < 16; u++) {
        int idx = u * 256 + tid;
        int r = idx >> 6, c = idx & 63;
        Qs[r * PAD + c] = Qh[(size_t)(q0 + r) * HD + c];
    }
    if (tid < 64) { rowM[tid] = -1e30f; rowL[tid] = 0.f; }

    const int ty = tid >> 4, tx = tid & 15;
    float o[4][4] = {};
    __syncthreads();

    for (int kt = 0; kt <= qb; kt++) {
        const int k0 = kt * 64;
        #pragma unroll
        for (int u = 0; u < 16; u++) {
            int idx = u * 256 + tid;
            int r = idx >> 6, c = idx & 63;
            Ks[r * PAD + c] = Kh[(size_t)(k0 + r) * HD + c];
            Vs[r * PAD + c] = Vh[(size_t)(k0 + r) * HD + c];
        }
        __syncthreads();

        float s[4][4] = {};
        #pragma unroll 4
        for (int d = 0; d < 64; d++) {
            float qv[4], kv[4];
            #pragma unroll
            for (int i = 0; i < 4; i++) qv[i] = Qs[(ty*4+i)*PAD + d];
            #pragma unroll
            for (int j = 0; j < 4; j++) kv[j] = Ks[(tx*4+j)*PAD + d];
            #pragma unroll
            for (int i = 0; i < 4; i++)
                #pragma unroll
                for (int j = 0; j < 4; j++)
                    s[i][j] = fmaf(qv[i], kv[j], s[i][j]);
        }
        if (kt == qb) {
            #pragma unroll
            for (int i = 0; i < 4; i++)
                #pragma unroll
                for (int j = 0; j < 4; j++)
                    if (k0 + tx*4+j > q0 + ty*4+i) s[i][j] = -1e30f;
        }
        #pragma unroll
        for (int i = 0; i < 4; i++)
            #pragma unroll
            for (int j = 0; j < 4; j++)
                Ss[(ty*4+i)*PAD + tx*4+j] = s[i][j];
        __syncthreads();

        {
            int r = tid >> 2, seg = tid & 3;
            float* srow = Ss + r * PAD + seg * 16;
            float mx = -1e30f;
            #pragma unroll
            for (int c = 0; c < 16; c++) mx = fmaxf(mx, srow[c]);
            mx = fmaxf(mx, __shfl_xor_sync(0xffffffffu, mx, 1));
            mx = fmaxf(mx, __shfl_xor_sync(0xffffffffu, mx, 2));
            float mo = rowM[r];
            float mn = fmaxf(mo, mx);
            float al = __expf(mo - mn);
            float ssum = 0.f;
            #pragma unroll
            for (int c = 0; c < 16; c++) {
                float p = __expf(srow[c] - mn);
                srow[c] = p;
                ssum += p;
            }
            ssum += __shfl_xor_sync(0xffffffffu, ssum, 1);
            ssum += __shfl_xor_sync(0xffffffffu, ssum, 2);
            if (seg == 0) {
                rowM[r] = mn;
                rowL[r] = rowL[r] * al + ssum;
                rowA[r] = al;
            }
        }
        __syncthreads();

        float al[4];
        #pragma unroll
        for (int i = 0; i < 4; i++) al[i] = rowA[ty*4+i];
        #pragma unroll
        for (int i = 0; i < 4; i++)
            #pragma unroll
            for (int j = 0; j < 4; j++) o[i][j] *= al[i];
        #pragma unroll 4
        for (int kk = 0; kk < 64; kk++) {
            float p[4], v[4];
            #pragma unroll
            for (int i = 0; i < 4; i++) p[i] = Ss[(ty*4+i)*PAD + kk];
            #pragma unroll
            for (int j = 0; j < 4; j++) v[j] = Vs[kk*PAD + tx*4+j];
            #pragma unroll
            for (int i = 0; i < 4; i++)
                #pragma unroll
                for (int j = 0; j < 4; j++)
                    o[i][j] = fmaf(p[i], v[j], o[i][j]);
        }
        __syncthreads();
    }

    const int b = bh >> 4, h = bh & 15;
    #pragma unroll
    for (int i = 0; i < 4; i++) {
        float inv = 1.f / rowL[ty*4+i];
        int t = q0 + ty*4+i;
        #pragma unroll
        for (int j = 0; j < 4; j++) {
            float val = o[i][j] * inv;
            size_t idx = ((size_t)(b * Tt + t)) * Cc + h * HD + tx*4+j;
            __nv_bfloat16 hh, ll;
            split_bf16(val, hh, ll);
            g_atth[idx] = hh;
            g_attl[idx] = ll;
        }
    }
}

// ---------------------------------------------------------------------------
extern "C" void kernel_launch(void* const* d_in, const int* in_sizes, int n_in,
                              void* d_out, int out_size) {
    const float* x        = (const float*)d_in[0];
    const float* ln_scale = (const float*)d_in[2];
    const float* ln_bias  = (const float*)d_in[3];
    const float* qkv_w    = (const float*)d_in[4];
    const float* qkv_b    = (const float*)d_in[5];
    const float* proj_w   = (const float*)d_in[6];
    const float* proj_b   = (const float*)d_in[7];
    float* out = (float*)d_out;

    const int gemm_smem = STAGE_E * 2 * (int)sizeof(__nv_bfloat16);   // 75776
    const int flash_smem = (4 * 64 * PAD + 3 * 64) * (int)sizeof(float);

    static bool attr_set = false;
    if (!attr_set) {
        cudaFuncSetAttribute(flash_kernel,
                             cudaFuncAttributeMaxDynamicSharedMemorySize, flash_smem);
        cudaFuncSetAttribute(mma_gemm<QKV_N, 0>,
                             cudaFuncAttributeMaxDynamicSharedMemorySize, gemm_smem);
        cudaFuncSetAttribute(mma_gemm<Cc, 1>,
                             cudaFuncAttributeMaxDynamicSharedMemorySize, gemm_smem);
        attr_set = true;
    }

    // Resolve ALL device-symbol scratch through cudaGetSymbolAddress before
    // using as kernel arguments (passing __device__ symbols directly from
    // host passes the host shadow address -> R3 bug).
    __nv_bfloat16 *xnh, *xnl, *wqh, *wql, *wph, *wpl, *atth, *attl;
    cudaGetSymbolAddress((void**)&xnh, g_xnh);
    cudaGetSymbolAddress((void**)&xnl, g_xnl);
    cudaGetSymbolAddress((void**)&wqh, g_wqh);
    cudaGetSymbolAddress((void**)&wql, g_wql);
    cudaGetSymbolAddress((void**)&wph, g_wph);
    cudaGetSymbolAddress((void**)&wpl, g_wpl);
    cudaGetSymbolAddress((void**)&atth, g_atth);
    cudaGetSymbolAddress((void**)&attl, g_attl);

    ln_kernel<<<MROWS, 256>>>(x, ln_scale, ln_bias);
    cvt_kernel<<<(Cc * QKV_N) / 1024, 256>>>(qkv_w, wqh, wql);
    cvt_kernel<<<(Cc * Cc) / 1024, 256>>>(proj_w, wph, wpl);

    mma_gemm<QKV_N, 0><<<dim3(QKV_N / 128, MROWS / 128), 256, gemm_smem>>>(
        xnh, xnl, wqh, wql, qkv_b, nullptr);
    flash_kernel<<<dim3(Tt / 64, Bb * NH), 256, flash_smem>>>();
    mma_gemm<Cc, 1><<<dim3(Cc / 128, MROWS / 128), 256, gemm_smem>>>(
        atth, attl, wph, wpl, proj_b, out);
}

// round 5
// speedup vs baseline: 2.7893x; 1.9010x over previous
#include <cuda_runtime.h>
#include <cuda_bf16.h>
#include <cstdint>
#include <math.h>

#define Bb 2
#define Tt 2048
#define Cc 1024
#define NH 16
#define HD 64
#define MROWS (Bb*Tt)          // 4096
#define QKV_N (3*Cc)           // 3072

// Scratch (device code references these directly; host never passes raw symbols)
__device__ __nv_bfloat16 g_xnh [MROWS*Cc];
__device__ __nv_bfloat16 g_xnl [MROWS*Cc];
__device__ __nv_bfloat16 g_wqh [Cc*QKV_N];
__device__ __nv_bfloat16 g_wql [Cc*QKV_N];
__device__ __nv_bfloat16 g_wph [Cc*Cc];
__device__ __nv_bfloat16 g_wpl [Cc*Cc];
__device__ __nv_bfloat16 g_qh [Bb*NH*Tt*HD];   // [b,h,t,d] (scaled by 1/8)
__device__ __nv_bfloat16 g_ql [Bb*NH*Tt*HD];
__device__ __nv_bfloat16 g_kh [Bb*NH*HD*Tt];   // [b,h,d,t]  (transposed!)
__device__ __nv_bfloat16 g_kl [Bb*NH*HD*Tt];
__device__ __nv_bfloat16 g_vh [Bb*NH*Tt*HD];   // [b,h,t,d]
__device__ __nv_bfloat16 g_vl [Bb*NH*Tt*HD];
__device__ __nv_bfloat16 g_atth[MROWS*Cc];
__device__ __nv_bfloat16 g_attl[MROWS*Cc];

__device__ __forceinline__ uint32_t smem_u32(const void* p) {
    return (uint32_t)__cvta_generic_to_shared(p);
}
__device__ __forceinline__ void cp16(uint32_t dst, const void* src) {
    asm volatile("cp.async.ca.shared.global [%0], [%1], 16;\n" :: "r"(dst), "l"(src));
}
__device__ __forceinline__ void cp_commit() { asm volatile("cp.async.commit_group;\n"); }
template<int N> __device__ __forceinline__ void cp_wait() {
    asm volatile("cp.async.wait_group %0;\n" :: "n"(N));
}
__device__ __forceinline__ void ldsm_x4(uint32_t a[4], uint32_t addr) {
    asm volatile("ldmatrix.sync.aligned.m8n8.x4.shared.b16 {%0,%1,%2,%3}, [%4];"
                 : "=r"(a[0]),"=r"(a[1]),"=r"(a[2]),"=r"(a[3]) : "r"(addr));
}
__device__ __forceinline__ void ldsm_x2t(uint32_t b[2], uint32_t addr) {
    asm volatile("ldmatrix.sync.aligned.m8n8.x2.trans.shared.b16 {%0,%1}, [%2];"
                 : "=r"(b[0]),"=r"(b[1]) : "r"(addr));
}
__device__ __forceinline__ void ldsm_x4t(uint32_t b[4], uint32_t addr) {
    asm volatile("ldmatrix.sync.aligned.m8n8.x4.trans.shared.b16 {%0,%1,%2,%3}, [%4];"
                 : "=r"(b[0]),"=r"(b[1]),"=r"(b[2]),"=r"(b[3]) : "r"(addr));
}
__device__ __forceinline__ void mma_bf16(float c[4], const uint32_t a[4], const uint32_t b0, const uint32_t b1) {
    asm volatile("mma.sync.aligned.m16n8k16.row.col.f32.bf16.bf16.f32 "
        "{%0,%1,%2,%3}, {%4,%5,%6,%7}, {%8,%9}, {%0,%1,%2,%3};"
        : "+f"(c[0]),"+f"(c[1]),"+f"(c[2]),"+f"(c[3])
        : "r"(a[0]),"r"(a[1]),"r"(a[2]),"r"(a[3]), "r"(b0),"r"(b1));
}
__device__ __forceinline__ void split_bf16(float v, __nv_bfloat16& h, __nv_bfloat16& l) {
    h = __float2bfloat16(v);
    l = __float2bfloat16(v - __bfloat162float(h));
}
__device__ __forceinline__ uint32_t pack_bf2(float x, float y) {
    __nv_bfloat162 t = __floats2bfloat162_rn(x, y);
    return *reinterpret_cast<uint32_t*>(&t);
}

// ---------------------------------------------------------------------------
// LayerNorm -> bf16 hi/lo
// ---------------------------------------------------------------------------
__device__ __forceinline__ float block_sum256(float v, float* red) {
    #pragma unroll
    for (int o = 16; o > 0; o >>= 1) v += __shfl_xor_sync(0xffffffffu, v, o);
    int w = threadIdx.x >> 5;
    if ((threadIdx.x & 31) == 0) red[w] = v;
    __syncthreads();
    float t = (threadIdx.x < 8) ? red[threadIdx.x] : 0.f;
    if (threadIdx.x < 32) {
        #pragma unroll
        for (int o = 4; o > 0; o >>= 1) t += __shfl_xor_sync(0xffffffffu, t, o);
        if (threadIdx.x == 0) red[0] = t;
    }
    __syncthreads();
    float r = red[0];
    __syncthreads();
    return r;
}

__global__ __launch_bounds__(256) void ln_kernel(
    const float* __restrict__ x, const float* __restrict__ scale,
    const float* __restrict__ bias) {
    __shared__ float red[8];
    const int row = blockIdx.x;
    const int tid = threadIdx.x;
    float4 v = reinterpret_cast<const float4*>(x + (size_t)row * Cc)[tid];
    float s = v.x + v.y + v.z + v.w;
    float mu = block_sum256(s, red) * (1.f / Cc);
    float dx = v.x - mu, dy = v.y - mu, dz = v.z - mu, dw = v.w - mu;
    float sq = dx*dx + dy*dy + dz*dz + dw*dw;
    float var = block_sum256(sq, red) * (1.f / Cc);
    float inv = rsqrtf(var + 1e-6f);
    float4 sc = reinterpret_cast<const float4*>(scale)[tid];
    float4 bi = reinterpret_cast<const float4*>(bias)[tid];
    float o[4];
    o[0] = dx * inv * sc.x + bi.x;
    o[1] = dy * inv * sc.y + bi.y;
    o[2] = dz * inv * sc.z + bi.z;
    o[3] = dw * inv * sc.w + bi.w;
    size_t base = (size_t)row * Cc + tid * 4;
    #pragma unroll
    for (int e = 0; e < 4; e++) {
        __nv_bfloat16 h, l;
        split_bf16(o[e], h, l);
        g_xnh[base + e] = h;
        g_xnl[base + e] = l;
    }
}

// ---------------------------------------------------------------------------
// fp32 -> bf16 hi/lo (weights)
// ---------------------------------------------------------------------------
__global__ __launch_bounds__(256) void cvt_kernel(
    const float* __restrict__ src, __nv_bfloat16* __restrict__ hi,
    __nv_bfloat16* __restrict__ lo) {
    int i = (blockIdx.x * 256 + threadIdx.x) * 4;
    float4 v = *reinterpret_cast<const float4*>(src + i);
    float a[4] = {v.x, v.y, v.z, v.w};
    #pragma unroll
    for (int e = 0; e < 4; e++) {
        __nv_bfloat16 h, l;
        split_bf16(a[e], h, l);
        hi[i + e] = h;
        lo[i + e] = l;
    }
}

// ---------------------------------------------------------------------------
// bf16x3 tensor-core GEMM (unchanged core); EPI=0 scatters Q/K/V bf16 hi/lo.
// ---------------------------------------------------------------------------
#define STAGE_E 18944
#define A_STR 40
#define B_STR 136

template<int ND, int EPI>
__global__ __launch_bounds__(256) void mma_gemm(
    const __nv_bfloat16* __restrict__ Ah_g, const __nv_bfloat16* __restrict__ Al_g,
    const __nv_bfloat16* __restrict__ Bh_g, const __nv_bfloat16* __restrict__ Bl_g,
    const float* __restrict__ bias, float* __restrict__ Cout)
{
    extern __shared__ __nv_bfloat16 smem[];
    const int tid = threadIdx.x;
    const int wid = tid >> 5, lane = tid & 31;
    const int wm = wid >> 2, wn = wid & 3;
    const int row0 = blockIdx.y * 128;
    const int col0 = blockIdx.x * 128;

    const int laneRowA = (lane & 7) + ((lane >> 3) & 1) * 8;
    const int laneColA = (lane >> 4) * 8;
    const int laneB = lane & 15;

    auto issue = [&](int it, int stage) {
        const int k0 = it * 32;
        __nv_bfloat16* s = smem + stage * STAGE_E;
        #pragma unroll
        for (int u = 0; u < 2; u++) {
            int c = tid + u * 256;
            int ar = c >> 2, ac = (c & 3) * 8;
            cp16(smem_u32(s + ar * A_STR + ac),
                 Ah_g + (size_t)(row0 + ar) * Cc + k0 + ac);
            cp16(smem_u32(s + 5120 + ar * A_STR + ac),
                 Al_g + (size_t)(row0 + ar) * Cc + k0 + ac);
            int br = c >> 4, bc = (c & 15) * 8;
            cp16(smem_u32(s + 10240 + br * B_STR + bc),
                 Bh_g + (size_t)(k0 + br) * ND + col0 + bc);
            cp16(smem_u32(s + 14592 + br * B_STR + bc),
                 Bl_g + (size_t)(k0 + br) * ND + col0 + bc);
        }
        cp_commit();
    };

    float acc[4][4][4] = {};
    issue(0, 0);

    #pragma unroll 1
    for (int it = 0; it < 32; it++) {
        const int buf = it & 1;
        if (it + 1 < 32) { issue(it + 1, buf ^ 1); cp_wait<1>(); }
        else             { cp_wait<0>(); }
        __syncthreads();
        __nv_bfloat16* sAh = smem + buf * STAGE_E;
        __nv_bfloat16* sAl = sAh + 5120;
        __nv_bfloat16* sBh = sAh + 10240;
        __nv_bfloat16* sBl = sAh + 14592;
        #pragma unroll
        for (int kk = 0; kk < 2; kk++) {
            uint32_t ah[4][4], al[4][4], bh[4][2], bl[4][2];
            #pragma unroll
            for (int i = 0; i < 4; i++) {
                int r = wm * 64 + i * 16 + laneRowA;
                int cA = kk * 16 + laneColA;
                ldsm_x4(ah[i], smem_u32(sAh + r * A_STR + cA));
                ldsm_x4(al[i], smem_u32(sAl + r * A_STR + cA));
            }
            #pragma unroll
            for (int j = 0; j < 4; j++) {
                int rB = kk * 16 + laneB;
                int cB = wn * 32 + j * 8;
                ldsm_x2t(bh[j], smem_u32(sBh + rB * B_STR + cB));
                ldsm_x2t(bl[j], smem_u32(sBl + rB * B_STR + cB));
            }
            #pragma unroll
            for (int i = 0; i < 4; i++)
                #pragma unroll
                for (int j = 0; j < 4; j++) {
                    mma_bf16(acc[i][j], ah[i], bh[j][0], bh[j][1]);
                    mma_bf16(acc[i][j], ah[i], bl[j][0], bl[j][1]);
                    mma_bf16(acc[i][j], al[i], bh[j][0], bh[j][1]);
                }
        }
        __syncthreads();
    }

    // Epilogue
    #pragma unroll
    for (int i = 0; i < 4; i++) {
        int rbase = row0 + wm * 64 + i * 16 + (lane >> 2);
        #pragma unroll
        for (int j = 0; j < 4; j++) {
            int nb = col0 + wn * 32 + j * 8 + (lane & 3) * 2;
            #pragma unroll
            for (int e = 0; e < 4; e++) {
                int m = rbase + (e >> 1) * 8;
                int n = nb + (e & 1);
                float val = acc[i][j][e] + bias[n];
                if (EPI == 1) {
                    Cout[(size_t)m * Cc + n] = val;
                } else {
                    int b = m >> 11, t = m & 2047;
                    int which = n >> 10, rr = n & 1023;
                    int h = rr >> 6, d = rr & 63;
                    int bh_i = b * NH + h;
                    __nv_bfloat16 vh_, vl_;
                    if (which == 0) {
                        split_bf16(val * 0.125f, vh_, vl_);
                        size_t idx = ((size_t)bh_i * Tt + t) * HD + d;
                        g_qh[idx] = vh_; g_ql[idx] = vl_;
                    } else if (which == 1) {
                        split_bf16(val, vh_, vl_);
                        size_t idx = ((size_t)bh_i * HD + d) * Tt + t;   // transposed
                        g_kh[idx] = vh_; g_kl[idx] = vl_;
                    } else {
                        split_bf16(val, vh_, vl_);
                        size_t idx = ((size_t)bh_i * Tt + t) * HD + d;
                        g_vh[idx] = vh_; g_vl[idx] = vl_;
                    }
                }
            }
        }
    }
}

// ---------------------------------------------------------------------------
// Tensor-core causal flash attention, bf16x3.
// BQ=64, BK=64, D=64. 128 threads = 4 warps, 16 query rows/warp.
// K smem [d][key], V smem [key][d], rows padded to 72 elems (144B).
// ---------------------------------------------------------------------------
#define FSTR 72
#define FSTAGE 18432            // elems per stage: 4 tiles * 64*72

__global__ __launch_bounds__(128) void flash_mma() {
    extern __shared__ __nv_bfloat16 fsm[];
    const int tid = threadIdx.x;
    const int w = tid >> 5, lane = tid & 31;
    const int qb = (int)gridDim.x - 1 - (int)blockIdx.x;   // big blocks first
    const int bh = blockIdx.y;
    const int q0 = qb * 64;

    const __nv_bfloat16* Qh_g = g_qh + (size_t)bh * Tt * HD;
    const __nv_bfloat16* Ql_g = g_ql + (size_t)bh * Tt * HD;
    const __nv_bfloat16* Kh_g = g_kh + (size_t)bh * HD * Tt;
    const __nv_bfloat16* Kl_g = g_kl + (size_t)bh * HD * Tt;
    const __nv_bfloat16* Vh_g = g_vh + (size_t)bh * Tt * HD;
    const __nv_bfloat16* Vl_g = g_vl + (size_t)bh * Tt * HD;

    const int laneRowA = (lane & 7) + ((lane >> 3) & 1) * 8;
    const int laneColA = (lane >> 4) * 8;
    const int lb16 = lane & 15;            // ldsm x4t row
    const int lbc = (lane >> 4) * 8;       // ldsm x4t col-block

    // ---- stage Q through stage-0 smem, extract fragments ----
    {
        #pragma unroll
        for (int u = 0; u < 4; u++) {
            int idx = tid + u * 128;       // 512 = 64 rows * 8 col-chunks
            int r = idx >> 3, c = (idx & 7) * 8;
            cp16(smem_u32(fsm + r * FSTR + c), Qh_g + (size_t)(q0 + r) * HD + c);
            cp16(smem_u32(fsm + 4608 + r * FSTR + c), Ql_g + (size_t)(q0 + r) * HD + c);
        }
        cp_commit();
        cp_wait<0>();
        __syncthreads();
    }
    uint32_t qfh[4][4], qfl[4][4];
    #pragma unroll
    for (int kk = 0; kk < 4; kk++) {
        int r = w * 16 + laneRowA;
        int c = kk * 16 + laneColA;
        ldsm_x4(qfh[kk], smem_u32(fsm + r * FSTR + c));
        ldsm_x4(qfl[kk], smem_u32(fsm + 4608 + r * FSTR + c));
    }
    __syncthreads();

    auto issueKV = [&](int kt, int stage) {
        const int k0 = kt * 64;
        __nv_bfloat16* s = fsm + stage * FSTAGE;
        #pragma unroll
        for (int u = 0; u < 4; u++) {
            int idx = tid + u * 128;
            int r = idx >> 3, c = (idx & 7) * 8;
            cp16(smem_u32(s + r * FSTR + c),          Kh_g + (size_t)r * Tt + k0 + c);
            cp16(smem_u32(s + 4608 + r * FSTR + c),   Kl_g + (size_t)r * Tt + k0 + c);
            cp16(smem_u32(s + 9216 + r * FSTR + c),   Vh_g + (size_t)(k0 + r) * HD + c);
            cp16(smem_u32(s + 13824 + r * FSTR + c),  Vl_g + (size_t)(k0 + r) * HD + c);
        }
        cp_commit();
    };

    float o[8][4] = {};
    float m0 = -1e30f, m1 = -1e30f, l0 = 0.f, l1 = 0.f;
    const int row0g = q0 + w * 16 + (lane >> 2);
    const int row1g = row0g + 8;

    issueKV(0, 0);

    #pragma unroll 1
    for (int kt = 0; kt <= qb; kt++) {
        const int buf = kt & 1;
        if (kt < qb) { issueKV(kt + 1, buf ^ 1); cp_wait<1>(); }
        else         { cp_wait<0>(); }
        __syncthreads();
        __nv_bfloat16* sKh = fsm + buf * FSTAGE;
        __nv_bfloat16* sKl = sKh + 4608;
        __nv_bfloat16* sVh = sKh + 9216;
        __nv_bfloat16* sVl = sKh + 13824;

        // ---- S = Q K^T (bf16x3) ----
        float s[8][4] = {};
        #pragma unroll
        for (int kk = 0; kk < 4; kk++) {
            #pragma unroll
            for (int jp = 0; jp < 4; jp++) {
                uint32_t bh4[4], bl4[4];
                uint32_t addr = smem_u32(sKh + (kk * 16 + lb16) * FSTR + jp * 16 + lbc);
                ldsm_x4t(bh4, addr);
                addr = smem_u32(sKl + (kk * 16 + lb16) * FSTR + jp * 16 + lbc);
                ldsm_x4t(bl4, addr);
                #pragma unroll
                for (int h2 = 0; h2 < 2; h2++) {
                    int j = jp * 2 + h2;
                    mma_bf16(s[j], qfh[kk], bh4[2*h2], bh4[2*h2+1]);
                    mma_bf16(s[j], qfh[kk], bl4[2*h2], bl4[2*h2+1]);
                    mma_bf16(s[j], qfl[kk], bh4[2*h2], bh4[2*h2+1]);
                }
            }
        }

        // ---- causal mask (last tile only) ----
        if (kt == qb) {
            const int k0 = kt * 64;
            #pragma unroll
            for (int j = 0; j < 8; j++) {
                int colb = k0 + j * 8 + (lane & 3) * 2;
                if (colb > row0g)     s[j][0] = -1e30f;
                if (colb + 1 > row0g) s[j][1] = -1e30f;
                if (colb > row1g)     s[j][2] = -1e30f;
                if (colb + 1 > row1g) s[j][3] = -1e30f;
            }
        }

        // ---- online softmax (per-warp, rows in quads) ----
        float tmax0 = -1e30f, tmax1 = -1e30f;
        #pragma unroll
        for (int j = 0; j < 8; j++) {
            tmax0 = fmaxf(tmax0, fmaxf(s[j][0], s[j][1]));
            tmax1 = fmaxf(tmax1, fmaxf(s[j][2], s[j][3]));
        }
        tmax0 = fmaxf(tmax0, __shfl_xor_sync(0xffffffffu, tmax0, 1));
        tmax0 = fmaxf(tmax0, __shfl_xor_sync(0xffffffffu, tmax0, 2));
        tmax1 = fmaxf(tmax1, __shfl_xor_sync(0xffffffffu, tmax1, 1));
        tmax1 = fmaxf(tmax1, __shfl_xor_sync(0xffffffffu, tmax1, 2));
        float mn0 = fmaxf(m0, tmax0), mn1 = fmaxf(m1, tmax1);
        float al0 = __expf(m0 - mn0), al1 = __expf(m1 - mn1);
        m0 = mn0; m1 = mn1;
        float ps0 = 0.f, ps1 = 0.f;
        #pragma unroll
        for (int j = 0; j < 8; j++) {
            s[j][0] = __expf(s[j][0] - mn0);
            s[j][1] = __expf(s[j][1] - mn0);
            s[j][2] = __expf(s[j][2] - mn1);
            s[j][3] = __expf(s[j][3] - mn1);
            ps0 += s[j][0] + s[j][1];
            ps1 += s[j][2] + s[j][3];
        }
        l0 = l0 * al0 + ps0;
        l1 = l1 * al1 + ps1;
        #pragma unroll
        for (int j = 0; j < 8; j++) {
            o[j][0] *= al0; o[j][1] *= al0;
            o[j][2] *= al1; o[j][3] *= al1;
        }

        // ---- O += P V (bf16x3); P fragments come straight from S regs ----
        #pragma unroll
        for (int kk = 0; kk < 4; kk++) {
            uint32_t aph[4], apl[4];
            {
                float x0 = s[2*kk][0],   x1 = s[2*kk][1];
                float x2 = s[2*kk][2],   x3 = s[2*kk][3];
                float y0 = s[2*kk+1][0], y1 = s[2*kk+1][1];
                float y2 = s[2*kk+1][2], y3 = s[2*kk+1][3];
                aph[0] = pack_bf2(x0, x1);
                aph[1] = pack_bf2(x2, x3);
                aph[2] = pack_bf2(y0, y1);
                aph[3] = pack_bf2(y2, y3);
                apl[0] = pack_bf2(x0 - __bfloat162float(__float2bfloat16(x0)),
                                  x1 - __bfloat162float(__float2bfloat16(x1)));
                apl[1] = pack_bf2(x2 - __bfloat162float(__float2bfloat16(x2)),
                                  x3 - __bfloat162float(__float2bfloat16(x3)));
                apl[2] = pack_bf2(y0 - __bfloat162float(__float2bfloat16(y0)),
                                  y1 - __bfloat162float(__float2bfloat16(y1)));
                apl[3] = pack_bf2(y2 - __bfloat162float(__float2bfloat16(y2)),
                                  y3 - __bfloat162float(__float2bfloat16(y3)));
            }
            #pragma unroll
            for (int jp = 0; jp < 4; jp++) {
                uint32_t vh4[4], vl4[4];
                uint32_t addr = smem_u32(sVh + (kk * 16 + lb16) * FSTR + jp * 16 + lbc);
                ldsm_x4t(vh4, addr);
                addr = smem_u32(sVl + (kk * 16 + lb16) * FSTR + jp * 16 + lbc);
                ldsm_x4t(vl4, addr);
                #pragma unroll
                for (int h2 = 0; h2 < 2; h2++) {
                    int j = jp * 2 + h2;
                    mma_bf16(o[j], aph, vh4[2*h2], vh4[2*h2+1]);
                    mma_bf16(o[j], aph, vl4[2*h2], vl4[2*h2+1]);
                    mma_bf16(o[j], apl, vh4[2*h2], vh4[2*h2+1]);
                }
            }
        }
        __syncthreads();
    }

    // ---- finalize: reduce l across quad, normalize, write hi/lo bf16 ----
    l0 += __shfl_xor_sync(0xffffffffu, l0, 1);
    l0 += __shfl_xor_sync(0xffffffffu, l0, 2);
    l1 += __shfl_xor_sync(0xffffffffu, l1, 1);
    l1 += __shfl_xor_sync(0xffffffffu, l1, 2);
    float inv0 = 1.f / l0, inv1 = 1.f / l1;

    const int b = bh >> 4, h = bh & 15;
    #pragma unroll
    for (int j = 0; j < 8; j++) {
        int col = h * HD + j * 8 + (lane & 3) * 2;
        {
            float v0 = o[j][0] * inv0, v1 = o[j][1] * inv0;
            size_t idx = ((size_t)(b * Tt + row0g)) * Cc + col;
            __nv_bfloat162 hh = __floats2bfloat162_rn(v0, v1);
            *reinterpret_cast<__nv_bfloat162*>(&g_atth[idx]) = hh;
            float lv0 = v0 - __bfloat162float(__float2bfloat16(v0));
            float lv1 = v1 - __bfloat162float(__float2bfloat16(v1));
            *reinterpret_cast<__nv_bfloat162*>(&g_attl[idx]) = __floats2bfloat162_rn(lv0, lv1);
        }
        {
            float v0 = o[j][2] * inv1, v1 = o[j][3] * inv1;
            size_t idx = ((size_t)(b * Tt + row1g)) * Cc + col;
            __nv_bfloat162 hh = __floats2bfloat162_rn(v0, v1);
            *reinterpret_cast<__nv_bfloat162*>(&g_atth[idx]) = hh;
            float lv0 = v0 - __bfloat162float(__float2bfloat16(v0));
            float lv1 = v1 - __bfloat162float(__float2bfloat16(v1));
            *reinterpret_cast<__nv_bfloat162*>(&g_attl[idx]) = __floats2bfloat162_rn(lv0, lv1);
        }
    }
}

// ---------------------------------------------------------------------------
extern "C" void kernel_launch(void* const* d_in, const int* in_sizes, int n_in,
                              void* d_out, int out_size) {
    const float* x        = (const float*)d_in[0];
    const float* ln_scale = (const float*)d_in[2];
    const float* ln_bias  = (const float*)d_in[3];
    const float* qkv_w    = (const float*)d_in[4];
    const float* qkv_b    = (const float*)d_in[5];
    const float* proj_w   = (const float*)d_in[6];
    const float* proj_b   = (const float*)d_in[7];
    float* out = (float*)d_out;

    const int gemm_smem  = STAGE_E * 2 * (int)sizeof(__nv_bfloat16);   // 75776
    const int flash_smem = FSTAGE * 2 * (int)sizeof(__nv_bfloat16);    // 73728

    static bool attr_set = false;
    if (!attr_set) {
        cudaFuncSetAttribute(flash_mma,
                             cudaFuncAttributeMaxDynamicSharedMemorySize, flash_smem);
        cudaFuncSetAttribute(mma_gemm<QKV_N, 0>,
                             cudaFuncAttributeMaxDynamicSharedMemorySize, gemm_smem);
        cudaFuncSetAttribute(mma_gemm<Cc, 1>,
                             cudaFuncAttributeMaxDynamicSharedMemorySize, gemm_smem);
        attr_set = true;
    }

    // Resolve device-symbol scratch for host-passed pointers.
    __nv_bfloat16 *xnh, *xnl, *wqh, *wql, *wph, *wpl, *atth, *attl;
    cudaGetSymbolAddress((void**)&xnh, g_xnh);
    cudaGetSymbolAddress((void**)&xnl, g_xnl);
    cudaGetSymbolAddress((void**)&wqh, g_wqh);
    cudaGetSymbolAddress((void**)&wql, g_wql);
    cudaGetSymbolAddress((void**)&wph, g_wph);
    cudaGetSymbolAddress((void**)&wpl, g_wpl);
    cudaGetSymbolAddress((void**)&atth, g_atth);
    cudaGetSymbolAddress((void**)&attl, g_attl);

    ln_kernel<<<MROWS, 256>>>(x, ln_scale, ln_bias);
    cvt_kernel<<<(Cc * QKV_N) / 1024, 256>>>(qkv_w, wqh, wql);
    cvt_kernel<<<(Cc * Cc) / 1024, 256>>>(proj_w, wph, wpl);

    mma_gemm<QKV_N, 0><<<dim3(QKV_N / 128, MROWS / 128), 256, gemm_smem>>>(
        xnh, xnl, wqh, wql, qkv_b, nullptr);
    flash_mma<<<dim3(Tt / 64, Bb * NH), 128, flash_smem>>>();
    mma_gemm<Cc, 1><<<dim3(Cc / 128, MROWS / 128), 256, gemm_smem>>>(
        atth, attl, wph, wpl, proj_b, out);
}

// round 7
// speedup vs baseline: 2.9954x; 1.0739x over previous
#include <cuda_runtime.h>
#include <cuda_bf16.h>
#include <cstdint>
#include <math.h>

#define Bb 2
#define Tt 2048
#define Cc 1024
#define NH 16
#define HD 64
#define MROWS (Bb*Tt)          // 4096
#define QKV_N (3*Cc)           // 3072

// Scratch
__device__ __nv_bfloat16 g_xnh [MROWS*Cc];
__device__ __nv_bfloat16 g_xnl [MROWS*Cc];
__device__ __nv_bfloat16 g_wqh [Cc*QKV_N];
__device__ __nv_bfloat16 g_wql [Cc*QKV_N];
__device__ __nv_bfloat16 g_wph [Cc*Cc];
__device__ __nv_bfloat16 g_wpl [Cc*Cc];
__device__ __nv_bfloat16 g_qh [Bb*NH*Tt*HD];   // [b,h,t,d] (scaled by 1/8)
__device__ __nv_bfloat16 g_ql [Bb*NH*Tt*HD];
__device__ __nv_bfloat16 g_kh [Bb*NH*HD*Tt];   // [b,h,d,t]  (transposed)
__device__ __nv_bfloat16 g_kl [Bb*NH*HD*Tt];
__device__ __nv_bfloat16 g_vh [Bb*NH*Tt*HD];   // [b,h,t,d]
__device__ __nv_bfloat16 g_vl [Bb*NH*Tt*HD];
__device__ __nv_bfloat16 g_atth[MROWS*Cc];
__device__ __nv_bfloat16 g_attl[MROWS*Cc];

__device__ __forceinline__ uint32_t smem_u32(const void* p) {
    return (uint32_t)__cvta_generic_to_shared(p);
}
__device__ __forceinline__ void cp16(uint32_t dst, const void* src) {
    asm volatile("cp.async.ca.shared.global [%0], [%1], 16;\n" :: "r"(dst), "l"(src));
}
__device__ __forceinline__ void cp_commit() { asm volatile("cp.async.commit_group;\n"); }
template<int N> __device__ __forceinline__ void cp_wait() {
    asm volatile("cp.async.wait_group %0;\n" :: "n"(N));
}
__device__ __forceinline__ void ldsm_x4(uint32_t a[4], uint32_t addr) {
    asm volatile("ldmatrix.sync.aligned.m8n8.x4.shared.b16 {%0,%1,%2,%3}, [%4];"
                 : "=r"(a[0]),"=r"(a[1]),"=r"(a[2]),"=r"(a[3]) : "r"(addr));
}
__device__ __forceinline__ void ldsm_x2t(uint32_t b[2], uint32_t addr) {
    asm volatile("ldmatrix.sync.aligned.m8n8.x2.trans.shared.b16 {%0,%1}, [%2];"
                 : "=r"(b[0]),"=r"(b[1]) : "r"(addr));
}
__device__ __forceinline__ void ldsm_x4t(uint32_t b[4], uint32_t addr) {
    asm volatile("ldmatrix.sync.aligned.m8n8.x4.trans.shared.b16 {%0,%1,%2,%3}, [%4];"
                 : "=r"(b[0]),"=r"(b[1]),"=r"(b[2]),"=r"(b[3]) : "r"(addr));
}
__device__ __forceinline__ void mma_bf16(float c[4], const uint32_t a[4], const uint32_t b0, const uint32_t b1) {
    asm volatile("mma.sync.aligned.m16n8k16.row.col.f32.bf16.bf16.f32 "
        "{%0,%1,%2,%3}, {%4,%5,%6,%7}, {%8,%9}, {%0,%1,%2,%3};"
        : "+f"(c[0]),"+f"(c[1]),"+f"(c[2]),"+f"(c[3])
        : "r"(a[0]),"r"(a[1]),"r"(a[2]),"r"(a[3]), "r"(b0),"r"(b1));
}
__device__ __forceinline__ void split_bf16(float v, __nv_bfloat16& h, __nv_bfloat16& l) {
    h = __float2bfloat16(v);
    l = __float2bfloat16(v - __bfloat162float(h));
}
__device__ __forceinline__ uint32_t pack_bf2(float x, float y) {
    __nv_bfloat162 t = __floats2bfloat162_rn(x, y);
    return *reinterpret_cast<uint32_t*>(&t);
}

// ---------------------------------------------------------------------------
// LayerNorm -> bf16 hi/lo
// ---------------------------------------------------------------------------
__device__ __forceinline__ float block_sum256(float v, float* red) {
    #pragma unroll
    for (int o = 16; o > 0; o >>= 1) v += __shfl_xor_sync(0xffffffffu, v, o);
    int w = threadIdx.x >> 5;
    if ((threadIdx.x & 31) == 0) red[w] = v;
    __syncthreads();
    float t = (threadIdx.x < 8) ? red[threadIdx.x] : 0.f;
    if (threadIdx.x < 32) {
        #pragma unroll
        for (int o = 4; o > 0; o >>= 1) t += __shfl_xor_sync(0xffffffffu, t, o);
        if (threadIdx.x == 0) red[0] = t;
    }
    __syncthreads();
    float r = red[0];
    __syncthreads();
    return r;
}

__global__ __launch_bounds__(256) void ln_kernel(
    const float* __restrict__ x, const float* __restrict__ scale,
    const float* __restrict__ bias) {
    __shared__ float red[8];
    const int row = blockIdx.x;
    const int tid = threadIdx.x;
    float4 v = reinterpret_cast<const float4*>(x + (size_t)row * Cc)[tid];
    float s = v.x + v.y + v.z + v.w;
    float mu = block_sum256(s, red) * (1.f / Cc);
    float dx = v.x - mu, dy = v.y - mu, dz = v.z - mu, dw = v.w - mu;
    float sq = dx*dx + dy*dy + dz*dz + dw*dw;
    float var = block_sum256(sq, red) * (1.f / Cc);
    float inv = rsqrtf(var + 1e-6f);
    float4 sc = reinterpret_cast<const float4*>(scale)[tid];
    float4 bi = reinterpret_cast<const float4*>(bias)[tid];
    float o[4];
    o[0] = dx * inv * sc.x + bi.x;
    o[1] = dy * inv * sc.y + bi.y;
    o[2] = dz * inv * sc.z + bi.z;
    o[3] = dw * inv * sc.w + bi.w;
    size_t base = (size_t)row * Cc + tid * 4;
    #pragma unroll
    for (int e = 0; e < 4; e++) {
        __nv_bfloat16 h, l;
        split_bf16(o[e], h, l);
        g_xnh[base + e] = h;
        g_xnl[base + e] = l;
    }
}

// ---------------------------------------------------------------------------
// fp32 -> bf16 hi/lo (weights)
// ---------------------------------------------------------------------------
__global__ __launch_bounds__(256) void cvt_kernel(
    const float* __restrict__ src, __nv_bfloat16* __restrict__ hi,
    __nv_bfloat16* __restrict__ lo) {
    int i = (blockIdx.x * 256 + threadIdx.x) * 4;
    float4 v = *reinterpret_cast<const float4*>(src + i);
    float a[4] = {v.x, v.y, v.z, v.w};
    #pragma unroll
    for (int e = 0; e < 4; e++) {
        __nv_bfloat16 h, l;
        split_bf16(a[e], h, l);
        hi[i + e] = h;
        lo[i + e] = l;
    }
}

// ---------------------------------------------------------------------------
// bf16x3 tensor-core GEMM: 128x128 block, 8 warps (2x4), warp tile 64x32.
// __launch_bounds__(256,2): cap regs at 128 so TWO CTAs fit per SM
// (R5 had 130 regs -> 1 CTA/SM, occ 12.5%).
// ---------------------------------------------------------------------------
#define STAGE_E 18944
#define A_STR 40
#define B_STR 136

template<int ND, int EPI>
__global__ __launch_bounds__(256, 2) void mma_gemm(
    const __nv_bfloat16* __restrict__ Ah_g, const __nv_bfloat16* __restrict__ Al_g,
    const __nv_bfloat16* __restrict__ Bh_g, const __nv_bfloat16* __restrict__ Bl_g,
    const float* __restrict__ bias, float* __restrict__ Cout)
{
    extern __shared__ __nv_bfloat16 smem[];
    const int tid = threadIdx.x;
    const int wid = tid >> 5, lane = tid & 31;
    const int wm = wid >> 2, wn = wid & 3;
    const int row0 = blockIdx.y * 128;
    const int col0 = blockIdx.x * 128;

    const int laneRowA = (lane & 7) + ((lane >> 3) & 1) * 8;
    const int laneColA = (lane >> 4) * 8;
    const int laneB = lane & 15;

    auto issue = [&](int it, int stage) {
        const int k0 = it * 32;
        __nv_bfloat16* s = smem + stage * STAGE_E;
        #pragma unroll
        for (int u = 0; u < 2; u++) {
            int c = tid + u * 256;
            int ar = c >> 2, ac = (c & 3) * 8;
            cp16(smem_u32(s + ar * A_STR + ac),
                 Ah_g + (size_t)(row0 + ar) * Cc + k0 + ac);
            cp16(smem_u32(s + 5120 + ar * A_STR + ac),
                 Al_g + (size_t)(row0 + ar) * Cc + k0 + ac);
            int br = c >> 4, bc = (c & 15) * 8;
            cp16(smem_u32(s + 10240 + br * B_STR + bc),
                 Bh_g + (size_t)(k0 + br) * ND + col0 + bc);
            cp16(smem_u32(s + 14592 + br * B_STR + bc),
                 Bl_g + (size_t)(k0 + br) * ND + col0 + bc);
        }
        cp_commit();
    };

    float acc[4][4][4] = {};
    issue(0, 0);

    #pragma unroll 1
    for (int it = 0; it < 32; it++) {
        const int buf = it & 1;
        if (it + 1 < 32) { issue(it + 1, buf ^ 1); cp_wait<1>(); }
        else             { cp_wait<0>(); }
        __syncthreads();
        __nv_bfloat16* sAh = smem + buf * STAGE_E;
        __nv_bfloat16* sAl = sAh + 5120;
        __nv_bfloat16* sBh = sAh + 10240;
        __nv_bfloat16* sBl = sAh + 14592;
        #pragma unroll
        for (int kk = 0; kk < 2; kk++) {
            uint32_t ah[4][4], al[4][4], bh[4][2], bl[4][2];
            #pragma unroll
            for (int i = 0; i < 4; i++) {
                int r = wm * 64 + i * 16 + laneRowA;
                int cA = kk * 16 + laneColA;
                ldsm_x4(ah[i], smem_u32(sAh + r * A_STR + cA));
                ldsm_x4(al[i], smem_u32(sAl + r * A_STR + cA));
            }
            #pragma unroll
            for (int j = 0; j < 4; j++) {
                int rB = kk * 16 + laneB;
                int cB = wn * 32 + j * 8;
                ldsm_x2t(bh[j], smem_u32(sBh + rB * B_STR + cB));
                ldsm_x2t(bl[j], smem_u32(sBl + rB * B_STR + cB));
            }
            #pragma unroll
            for (int i = 0; i < 4; i++)
                #pragma unroll
                for (int j = 0; j < 4; j++) {
                    mma_bf16(acc[i][j], ah[i], bh[j][0], bh[j][1]);
                    mma_bf16(acc[i][j], ah[i], bl[j][0], bl[j][1]);
                    mma_bf16(acc[i][j], al[i], bh[j][0], bh[j][1]);
                }
        }
        __syncthreads();
    }

    // Epilogue
    #pragma unroll
    for (int i = 0; i < 4; i++) {
        int rbase = row0 + wm * 64 + i * 16 + (lane >> 2);
        #pragma unroll
        for (int j = 0; j < 4; j++) {
            int nb = col0 + wn * 32 + j * 8 + (lane & 3) * 2;
            #pragma unroll
            for (int e = 0; e < 4; e++) {
                int m = rbase + (e >> 1) * 8;
                int n = nb + (e & 1);
                float val = acc[i][j][e] + bias[n];
                if (EPI == 1) {
                    Cout[(size_t)m * Cc + n] = val;
                } else {
                    int b = m >> 11, t = m & 2047;
                    int which = n >> 10, rr = n & 1023;
                    int h = rr >> 6, d = rr & 63;
                    int bh_i = b * NH + h;
                    __nv_bfloat16 vh_, vl_;
                    if (which == 0) {
                        split_bf16(val * 0.125f, vh_, vl_);
                        size_t idx = ((size_t)bh_i * Tt + t) * HD + d;
                        g_qh[idx] = vh_; g_ql[idx] = vl_;
                    } else if (which == 1) {
                        split_bf16(val, vh_, vl_);
                        size_t idx = ((size_t)bh_i * HD + d) * Tt + t;   // transposed
                        g_kh[idx] = vh_; g_kl[idx] = vl_;
                    } else {
                        split_bf16(val, vh_, vl_);
                        size_t idx = ((size_t)bh_i * Tt + t) * HD + d;
                        g_vh[idx] = vh_; g_vl[idx] = vl_;
                    }
                }
            }
        }
    }
}

// ---------------------------------------------------------------------------
// Tensor-core causal flash attention, bf16x3.
// __launch_bounds__(128,3): 3 CTAs/SM (smem 73.7KB*3 fits 227KB; regs <=170).
// ---------------------------------------------------------------------------
#define FSTR 72
#define FSTAGE 18432

__global__ __launch_bounds__(128, 3) void flash_mma() {
    extern __shared__ __nv_bfloat16 fsm[];
    const int tid = threadIdx.x;
    const int w = tid >> 5, lane = tid & 31;
    const int qb = (int)gridDim.x - 1 - (int)blockIdx.x;
    const int bh = blockIdx.y;
    const int q0 = qb * 64;

    const __nv_bfloat16* Qh_g = g_qh + (size_t)bh * Tt * HD;
    const __nv_bfloat16* Ql_g = g_ql + (size_t)bh * Tt * HD;
    const __nv_bfloat16* Kh_g = g_kh + (size_t)bh * HD * Tt;
    const __nv_bfloat16* Kl_g = g_kl + (size_t)bh * HD * Tt;
    const __nv_bfloat16* Vh_g = g_vh + (size_t)bh * Tt * HD;
    const __nv_bfloat16* Vl_g = g_vl + (size_t)bh * Tt * HD;

    const int laneRowA = (lane & 7) + ((lane >> 3) & 1) * 8;
    const int laneColA = (lane >> 4) * 8;
    const int lb16 = lane & 15;
    const int lbc = (lane >> 4) * 8;

    {
        #pragma unroll
        for (int u = 0; u < 4; u++) {
            int idx = tid + u * 128;
            int r = idx >> 3, c = (idx & 7) * 8;
            cp16(smem_u32(fsm + r * FSTR + c), Qh_g + (size_t)(q0 + r) * HD + c);
            cp16(smem_u32(fsm + 4608 + r * FSTR + c), Ql_g + (size_t)(q0 + r) * HD + c);
        }
        cp_commit();
        cp_wait<0>();
        __syncthreads();
    }
    uint32_t qfh[4][4], qfl[4][4];
    #pragma unroll
    for (int kk = 0; kk < 4; kk++) {
        int r = w * 16 + laneRowA;
        int c = kk * 16 + laneColA;
        ldsm_x4(qfh[kk], smem_u32(fsm + r * FSTR + c));
        ldsm_x4(qfl[kk], smem_u32(fsm + 4608 + r * FSTR + c));
    }
    __syncthreads();

    auto issueKV = [&](int kt, int stage) {
        const int k0 = kt * 64;
        __nv_bfloat16* s = fsm + stage * FSTAGE;
        #pragma unroll
        for (int u = 0; u < 4; u++) {
            int idx = tid + u * 128;
            int r = idx >> 3, c = (idx & 7) * 8;
            cp16(smem_u32(s + r * FSTR + c),          Kh_g + (size_t)r * Tt + k0 + c);
            cp16(smem_u32(s + 4608 + r * FSTR + c),   Kl_g + (size_t)r * Tt + k0 + c);
            cp16(smem_u32(s + 9216 + r * FSTR + c),   Vh_g + (size_t)(k0 + r) * HD + c);
            cp16(smem_u32(s + 13824 + r * FSTR + c),  Vl_g + (size_t)(k0 + r) * HD + c);
        }
        cp_commit();
    };

    float o[8][4] = {};
    float m0 = -1e30f, m1 = -1e30f, l0 = 0.f, l1 = 0.f;
    const int row0g = q0 + w * 16 + (lane >> 2);
    const int row1g = row0g + 8;

    issueKV(0, 0);

    #pragma unroll 1
    for (int kt = 0; kt <= qb; kt++) {
        const int buf = kt & 1;
        if (kt < qb) { issueKV(kt + 1, buf ^ 1); cp_wait<1>(); }
        else         { cp_wait<0>(); }
        __syncthreads();
        __nv_bfloat16* sKh = fsm + buf * FSTAGE;
        __nv_bfloat16* sKl = sKh + 4608;
        __nv_bfloat16* sVh = sKh + 9216;
        __nv_bfloat16* sVl = sKh + 13824;

        float s[8][4] = {};
        #pragma unroll
        for (int kk = 0; kk < 4; kk++) {
            #pragma unroll
            for (int jp = 0; jp < 4; jp++) {
                uint32_t bh4[4], bl4[4];
                uint32_t addr = smem_u32(sKh + (kk * 16 + lb16) * FSTR + jp * 16 + lbc);
                ldsm_x4t(bh4, addr);
                addr = smem_u32(sKl + (kk * 16 + lb16) * FSTR + jp * 16 + lbc);
                ldsm_x4t(bl4, addr);
                #pragma unroll
                for (int h2 = 0; h2 < 2; h2++) {
                    int j = jp * 2 + h2;
                    mma_bf16(s[j], qfh[kk], bh4[2*h2], bh4[2*h2+1]);
                    mma_bf16(s[j], qfh[kk], bl4[2*h2], bl4[2*h2+1]);
                    mma_bf16(s[j], qfl[kk], bh4[2*h2], bh4[2*h2+1]);
                }
            }
        }

        if (kt == qb) {
            const int k0 = kt * 64;
            #pragma unroll
            for (int j = 0; j < 8; j++) {
                int colb = k0 + j * 8 + (lane & 3) * 2;
                if (colb > row0g)     s[j][0] = -1e30f;
                if (colb + 1 > row0g) s[j][1] = -1e30f;
                if (colb > row1g)     s[j][2] = -1e30f;
                if (colb + 1 > row1g) s[j][3] = -1e30f;
            }
        }

        float tmax0 = -1e30f, tmax1 = -1e30f;
        #pragma unroll
        for (int j = 0; j < 8; j++) {
            tmax0 = fmaxf(tmax0, fmaxf(s[j][0], s[j][1]));
            tmax1 = fmaxf(tmax1, fmaxf(s[j][2], s[j][3]));
        }
        tmax0 = fmaxf(tmax0, __shfl_xor_sync(0xffffffffu, tmax0, 1));
        tmax0 = fmaxf(tmax0, __shfl_xor_sync(0xffffffffu, tmax0, 2));
        tmax1 = fmaxf(tmax1, __shfl_xor_sync(0xffffffffu, tmax1, 1));
        tmax1 = fmaxf(tmax1, __shfl_xor_sync(0xffffffffu, tmax1, 2));
        float mn0 = fmaxf(m0, tmax0), mn1 = fmaxf(m1, tmax1);
        float al0 = __expf(m0 - mn0), al1 = __expf(m1 - mn1);
        m0 = mn0; m1 = mn1;
        float ps0 = 0.f, ps1 = 0.f;
        #pragma unroll
        for (int j = 0; j < 8; j++) {
            s[j][0] = __expf(s[j][0] - mn0);
            s[j][1] = __expf(s[j][1] - mn0);
            s[j][2] = __expf(s[j][2] - mn1);
            s[j][3] = __expf(s[j][3] - mn1);
            ps0 += s[j][0] + s[j][1];
            ps1 += s[j][2] + s[j][3];
        }
        l0 = l0 * al0 + ps0;
        l1 = l1 * al1 + ps1;
        #pragma unroll
        for (int j = 0; j < 8; j++) {
            o[j][0] *= al0; o[j][1] *= al0;
            o[j][2] *= al1; o[j][3] *= al1;
        }

        #pragma unroll
        for (int kk = 0; kk < 4; kk++) {
            uint32_t aph[4], apl[4];
            {
                float x0 = s[2*kk][0],   x1 = s[2*kk][1];
                float x2 = s[2*kk][2],   x3 = s[2*kk][3];
                float y0 = s[2*kk+1][0], y1 = s[2*kk+1][1];
                float y2 = s[2*kk+1][2], y3 = s[2*kk+1][3];
                aph[0] = pack_bf2(x0, x1);
                aph[1] = pack_bf2(x2, x3);
                aph[2] = pack_bf2(y0, y1);
                aph[3] = pack_bf2(y2, y3);
                apl[0] = pack_bf2(x0 - __bfloat162float(__float2bfloat16(x0)),
                                  x1 - __bfloat162float(__float2bfloat16(x1)));
                apl[1] = pack_bf2(x2 - __bfloat162float(__float2bfloat16(x2)),
                                  x3 - __bfloat162float(__float2bfloat16(x3)));
                apl[2] = pack_bf2(y0 - __bfloat162float(__float2bfloat16(y0)),
                                  y1 - __bfloat162float(__float2bfloat16(y1)));
                apl[3] = pack_bf2(y2 - __bfloat162float(__float2bfloat16(y2)),
                                  y3 - __bfloat162float(__float2bfloat16(y3)));
            }
            #pragma unroll
            for (int jp = 0; jp < 4; jp++) {
                uint32_t vh4[4], vl4[4];
                uint32_t addr = smem_u32(sVh + (kk * 16 + lb16) * FSTR + jp * 16 + lbc);
                ldsm_x4t(vh4, addr);
                addr = smem_u32(sVl + (kk * 16 + lb16) * FSTR + jp * 16 + lbc);
                ldsm_x4t(vl4, addr);
                #pragma unroll
                for (int h2 = 0; h2 < 2; h2++) {
                    int j = jp * 2 + h2;
                    mma_bf16(o[j], aph, vh4[2*h2], vh4[2*h2+1]);
                    mma_bf16(o[j], aph, vl4[2*h2], vl4[2*h2+1]);
                    mma_bf16(o[j], apl, vh4[2*h2], vh4[2*h2+1]);
                }
            }
        }
        __syncthreads();
    }

    l0 += __shfl_xor_sync(0xffffffffu, l0, 1);
    l0 += __shfl_xor_sync(0xffffffffu, l0, 2);
    l1 += __shfl_xor_sync(0xffffffffu, l1, 1);
    l1 += __shfl_xor_sync(0xffffffffu, l1, 2);
    float inv0 = 1.f / l0, inv1 = 1.f / l1;

    const int b = bh >> 4, h = bh & 15;
    #pragma unroll
    for (int j = 0; j < 8; j++) {
        int col = h * HD + j * 8 + (lane & 3) * 2;
        {
            float v0 = o[j][0] * inv0, v1 = o[j][1] * inv0;
            size_t idx = ((size_t)(b * Tt + row0g)) * Cc + col;
            *reinterpret_cast<__nv_bfloat162*>(&g_atth[idx]) = __floats2bfloat162_rn(v0, v1);
            float lv0 = v0 - __bfloat162float(__float2bfloat16(v0));
            float lv1 = v1 - __bfloat162float(__float2bfloat16(v1));
            *reinterpret_cast<__nv_bfloat162*>(&g_attl[idx]) = __floats2bfloat162_rn(lv0, lv1);
        }
        {
            float v0 = o[j][2] * inv1, v1 = o[j][3] * inv1;
            size_t idx = ((size_t)(b * Tt + row1g)) * Cc + col;
            *reinterpret_cast<__nv_bfloat162*>(&g_atth[idx]) = __floats2bfloat162_rn(v0, v1);
            float lv0 = v0 - __bfloat162float(__float2bfloat16(v0));
            float lv1 = v1 - __bfloat162float(__float2bfloat16(v1));
            *reinterpret_cast<__nv_bfloat162*>(&g_attl[idx]) = __floats2bfloat162_rn(lv0, lv1);
        }
    }
}

// ---------------------------------------------------------------------------
extern "C" void kernel_launch(void* const* d_in, const int* in_sizes, int n_in,
                              void* d_out, int out_size) {
    const float* x        = (const float*)d_in[0];
    const float* ln_scale = (const float*)d_in[2];
    const float* ln_bias  = (const float*)d_in[3];
    const float* qkv_w    = (const float*)d_in[4];
    const float* qkv_b    = (const float*)d_in[5];
    const float* proj_w   = (const float*)d_in[6];
    const float* proj_b   = (const float*)d_in[7];
    float* out = (float*)d_out;

    const int gemm_smem  = STAGE_E * 2 * (int)sizeof(__nv_bfloat16);   // 75776
    const int flash_smem = FSTAGE * 2 * (int)sizeof(__nv_bfloat16);    // 73728

    static bool attr_set = false;
    if (!attr_set) {
        cudaFuncSetAttribute(flash_mma,
                             cudaFuncAttributeMaxDynamicSharedMemorySize, flash_smem);
        cudaFuncSetAttribute(mma_gemm<QKV_N, 0>,
                             cudaFuncAttributeMaxDynamicSharedMemorySize, gemm_smem);
        cudaFuncSetAttribute(mma_gemm<Cc, 1>,
                             cudaFuncAttributeMaxDynamicSharedMemorySize, gemm_smem);
        attr_set = true;
    }

    __nv_bfloat16 *xnh, *xnl, *wqh, *wql, *wph, *wpl, *atth, *attl;
    cudaGetSymbolAddress((void**)&xnh, g_xnh);
    cudaGetSymbolAddress((void**)&xnl, g_xnl);
    cudaGetSymbolAddress((void**)&wqh, g_wqh);
    cudaGetSymbolAddress((void**)&wql, g_wql);
    cudaGetSymbolAddress((void**)&wph, g_wph);
    cudaGetSymbolAddress((void**)&wpl, g_wpl);
    cudaGetSymbolAddress((void**)&atth, g_atth);
    cudaGetSymbolAddress((void**)&attl, g_attl);

    ln_kernel<<<MROWS, 256>>>(x, ln_scale, ln_bias);
    cvt_kernel<<<(Cc * QKV_N) / 1024, 256>>>(qkv_w, wqh, wql);
    cvt_kernel<<<(Cc * Cc) / 1024, 256>>>(proj_w, wph, wpl);

    mma_gemm<QKV_N, 0><<<dim3(QKV_N / 128, MROWS / 128), 256, gemm_smem>>>(
        xnh, xnl, wqh, wql, qkv_b, nullptr);
    flash_mma<<<dim3(Tt / 64, Bb * NH), 128, flash_smem>>>();
    mma_gemm<Cc, 1><<<dim3(Cc / 128, MROWS / 128), 256, gemm_smem>>>(
        atth, attl, wph, wpl, proj_b, out);
}

// round 8
// speedup vs baseline: 3.5470x; 1.1842x over previous
#include <cuda_runtime.h>
#include <cuda_bf16.h>
#include <cuda_fp16.h>
#include <cstdint>
#include <math.h>

#define Bb 2
#define Tt 2048
#define Cc 1024
#define NH 16
#define HD 64
#define MROWS (Bb*Tt)          // 4096
#define QKV_N (3*Cc)           // 3072

// Scratch
__device__ __half g_xnh [MROWS*Cc];            // LN out hi (fp16)
__device__ __half g_xnl [MROWS*Cc];            // LN out lo (fp16)
__device__ __half g_wq  [Cc*QKV_N];            // qkv W single fp16
__device__ __half g_wp  [Cc*Cc];               // proj W single fp16
__device__ __nv_bfloat16 g_qh [Bb*NH*Tt*HD];   // [b,h,t,d] (scaled 1/8)
__device__ __nv_bfloat16 g_ql [Bb*NH*Tt*HD];
__device__ __nv_bfloat16 g_kh [Bb*NH*HD*Tt];   // [b,h,d,t]  (transposed)
__device__ __nv_bfloat16 g_kl [Bb*NH*HD*Tt];
__device__ __nv_bfloat16 g_vh [Bb*NH*Tt*HD];
__device__ __nv_bfloat16 g_vl [Bb*NH*Tt*HD];
__device__ __half g_atth[MROWS*Cc];            // attention out hi (fp16)
__device__ __half g_attl[MROWS*Cc];            // attention out lo (fp16)

__device__ __forceinline__ uint32_t smem_u32(const void* p) {
    return (uint32_t)__cvta_generic_to_shared(p);
}
__device__ __forceinline__ void cp16(uint32_t dst, const void* src) {
    asm volatile("cp.async.ca.shared.global [%0], [%1], 16;\n" :: "r"(dst), "l"(src));
}
__device__ __forceinline__ void cp_commit() { asm volatile("cp.async.commit_group;\n"); }
template<int N> __device__ __forceinline__ void cp_wait() {
    asm volatile("cp.async.wait_group %0;\n" :: "n"(N));
}
__device__ __forceinline__ void ldsm_x4(uint32_t a[4], uint32_t addr) {
    asm volatile("ldmatrix.sync.aligned.m8n8.x4.shared.b16 {%0,%1,%2,%3}, [%4];"
                 : "=r"(a[0]),"=r"(a[1]),"=r"(a[2]),"=r"(a[3]) : "r"(addr));
}
__device__ __forceinline__ void ldsm_x2t(uint32_t b[2], uint32_t addr) {
    asm volatile("ldmatrix.sync.aligned.m8n8.x2.trans.shared.b16 {%0,%1}, [%2];"
                 : "=r"(b[0]),"=r"(b[1]) : "r"(addr));
}
__device__ __forceinline__ void ldsm_x4t(uint32_t b[4], uint32_t addr) {
    asm volatile("ldmatrix.sync.aligned.m8n8.x4.trans.shared.b16 {%0,%1,%2,%3}, [%4];"
                 : "=r"(b[0]),"=r"(b[1]),"=r"(b[2]),"=r"(b[3]) : "r"(addr));
}
__device__ __forceinline__ void mma_bf16(float c[4], const uint32_t a[4], const uint32_t b0, const uint32_t b1) {
    asm volatile("mma.sync.aligned.m16n8k16.row.col.f32.bf16.bf16.f32 "
        "{%0,%1,%2,%3}, {%4,%5,%6,%7}, {%8,%9}, {%0,%1,%2,%3};"
        : "+f"(c[0]),"+f"(c[1]),"+f"(c[2]),"+f"(c[3])
        : "r"(a[0]),"r"(a[1]),"r"(a[2]),"r"(a[3]), "r"(b0),"r"(b1));
}
__device__ __forceinline__ void mma_f16(float c[4], const uint32_t a[4], const uint32_t b0, const uint32_t b1) {
    asm volatile("mma.sync.aligned.m16n8k16.row.col.f32.f16.f16.f32 "
        "{%0,%1,%2,%3}, {%4,%5,%6,%7}, {%8,%9}, {%0,%1,%2,%3};"
        : "+f"(c[0]),"+f"(c[1]),"+f"(c[2]),"+f"(c[3])
        : "r"(a[0]),"r"(a[1]),"r"(a[2]),"r"(a[3]), "r"(b0),"r"(b1));
}
__device__ __forceinline__ void split_bf16(float v, __nv_bfloat16& h, __nv_bfloat16& l) {
    h = __float2bfloat16(v);
    l = __float2bfloat16(v - __bfloat162float(h));
}
__device__ __forceinline__ void split_fp16(float v, __half& h, __half& l) {
    h = __float2half_rn(v);
    l = __float2half_rn(v - __half2float(h));
}
__device__ __forceinline__ uint32_t pack_bf2(float x, float y) {
    __nv_bfloat162 t = __floats2bfloat162_rn(x, y);
    return *reinterpret_cast<uint32_t*>(&t);
}

// ---------------------------------------------------------------------------
// LayerNorm -> fp16 hi/lo
// ---------------------------------------------------------------------------
__device__ __forceinline__ float block_sum256(float v, float* red) {
    #pragma unroll
    for (int o = 16; o > 0; o >>= 1) v += __shfl_xor_sync(0xffffffffu, v, o);
    int w = threadIdx.x >> 5;
    if ((threadIdx.x & 31) == 0) red[w] = v;
    __syncthreads();
    float t = (threadIdx.x < 8) ? red[threadIdx.x] : 0.f;
    if (threadIdx.x < 32) {
        #pragma unroll
        for (int o = 4; o > 0; o >>= 1) t += __shfl_xor_sync(0xffffffffu, t, o);
        if (threadIdx.x == 0) red[0] = t;
    }
    __syncthreads();
    float r = red[0];
    __syncthreads();
    return r;
}

__global__ __launch_bounds__(256) void ln_kernel(
    const float* __restrict__ x, const float* __restrict__ scale,
    const float* __restrict__ bias) {
    __shared__ float red[8];
    const int row = blockIdx.x;
    const int tid = threadIdx.x;
    float4 v = reinterpret_cast<const float4*>(x + (size_t)row * Cc)[tid];
    float s = v.x + v.y + v.z + v.w;
    float mu = block_sum256(s, red) * (1.f / Cc);
    float dx = v.x - mu, dy = v.y - mu, dz = v.z - mu, dw = v.w - mu;
    float sq = dx*dx + dy*dy + dz*dz + dw*dw;
    float var = block_sum256(sq, red) * (1.f / Cc);
    float inv = rsqrtf(var + 1e-6f);
    float4 sc = reinterpret_cast<const float4*>(scale)[tid];
    float4 bi = reinterpret_cast<const float4*>(bias)[tid];
    float o[4];
    o[0] = dx * inv * sc.x + bi.x;
    o[1] = dy * inv * sc.y + bi.y;
    o[2] = dz * inv * sc.z + bi.z;
    o[3] = dw * inv * sc.w + bi.w;
    size_t base = (size_t)row * Cc + tid * 4;
    #pragma unroll
    for (int e = 0; e < 4; e++) {
        __half h, l;
        split_fp16(o[e], h, l);
        g_xnh[base + e] = h;
        g_xnl[base + e] = l;
    }
}

// ---------------------------------------------------------------------------
// fp32 -> fp16 single (weights)
// ---------------------------------------------------------------------------
__global__ __launch_bounds__(256) void cvt_kernel(
    const float* __restrict__ src, __half* __restrict__ dst) {
    int i = (blockIdx.x * 256 + threadIdx.x) * 4;
    float4 v = *reinterpret_cast<const float4*>(src + i);
    __half2 a = __floats2half2_rn(v.x, v.y);
    __half2 b = __floats2half2_rn(v.z, v.w);
    *reinterpret_cast<__half2*>(&dst[i])     = a;
    *reinterpret_cast<__half2*>(&dst[i + 2]) = b;
}

// ---------------------------------------------------------------------------
// fp16 2-term tensor-core GEMM: 128x128 block, 8 warps (2x4), warp tile 64x32.
// C = Ah*B + Al*B, fp32 accum. A split fp16 hi/lo, B single fp16.
// Smem per stage (elems): Ah[128][40]=5120, Al=5120, B[32][136]=4352 -> 14592
// ---------------------------------------------------------------------------
#define STAGE_E 14592
#define A_STR 40
#define B_STR 136

template<int ND, int EPI>
__global__ __launch_bounds__(256, 2) void mma_gemm(
    const __half* __restrict__ Ah_g, const __half* __restrict__ Al_g,
    const __half* __restrict__ B_g,
    const float* __restrict__ bias, float* __restrict__ Cout)
{
    extern __shared__ __half smem[];
    const int tid = threadIdx.x;
    const int wid = tid >> 5, lane = tid & 31;
    const int wm = wid >> 2, wn = wid & 3;
    const int row0 = blockIdx.y * 128;
    const int col0 = blockIdx.x * 128;

    const int laneRowA = (lane & 7) + ((lane >> 3) & 1) * 8;
    const int laneColA = (lane >> 4) * 8;
    const int laneB = lane & 15;

    auto issue = [&](int it, int stage) {
        const int k0 = it * 32;
        __half* s = smem + stage * STAGE_E;
        #pragma unroll
        for (int u = 0; u < 2; u++) {
            int c = tid + u * 256;
            int ar = c >> 2, ac = (c & 3) * 8;
            cp16(smem_u32(s + ar * A_STR + ac),
                 Ah_g + (size_t)(row0 + ar) * Cc + k0 + ac);
            cp16(smem_u32(s + 5120 + ar * A_STR + ac),
                 Al_g + (size_t)(row0 + ar) * Cc + k0 + ac);
            int br = c >> 4, bc = (c & 15) * 8;
            cp16(smem_u32(s + 10240 + br * B_STR + bc),
                 B_g + (size_t)(k0 + br) * ND + col0 + bc);
        }
        cp_commit();
    };

    float acc[4][4][4] = {};
    issue(0, 0);

    #pragma unroll 1
    for (int it = 0; it < 32; it++) {
        const int buf = it & 1;
        if (it + 1 < 32) { issue(it + 1, buf ^ 1); cp_wait<1>(); }
        else             { cp_wait<0>(); }
        __syncthreads();
        __half* sAh = smem + buf * STAGE_E;
        __half* sAl = sAh + 5120;
        __half* sB  = sAh + 10240;
        #pragma unroll
        for (int kk = 0; kk < 2; kk++) {
            uint32_t ah[4][4], al[4][4], bb[4][2];
            #pragma unroll
            for (int i = 0; i < 4; i++) {
                int r = wm * 64 + i * 16 + laneRowA;
                int cA = kk * 16 + laneColA;
                ldsm_x4(ah[i], smem_u32(sAh + r * A_STR + cA));
                ldsm_x4(al[i], smem_u32(sAl + r * A_STR + cA));
            }
            #pragma unroll
            for (int j = 0; j < 4; j++) {
                int rB = kk * 16 + laneB;
                int cB = wn * 32 + j * 8;
                ldsm_x2t(bb[j], smem_u32(sB + rB * B_STR + cB));
            }
            #pragma unroll
            for (int i = 0; i < 4; i++)
                #pragma unroll
                for (int j = 0; j < 4; j++) {
                    mma_f16(acc[i][j], ah[i], bb[j][0], bb[j][1]);
                    mma_f16(acc[i][j], al[i], bb[j][0], bb[j][1]);
                }
        }
        __syncthreads();
    }

    // Epilogue
    #pragma unroll
    for (int i = 0; i < 4; i++) {
        int rbase = row0 + wm * 64 + i * 16 + (lane >> 2);
        #pragma unroll
        for (int j = 0; j < 4; j++) {
            int nb = col0 + wn * 32 + j * 8 + (lane & 3) * 2;
            #pragma unroll
            for (int e = 0; e < 4; e++) {
                int m = rbase + (e >> 1) * 8;
                int n = nb + (e & 1);
                float val = acc[i][j][e] + bias[n];
                if (EPI == 1) {
                    Cout[(size_t)m * Cc + n] = val;
                } else {
                    int b = m >> 11, t = m & 2047;
                    int which = n >> 10, rr = n & 1023;
                    int h = rr >> 6, d = rr & 63;
                    int bh_i = b * NH + h;
                    __nv_bfloat16 vh_, vl_;
                    if (which == 0) {
                        split_bf16(val * 0.125f, vh_, vl_);
                        size_t idx = ((size_t)bh_i * Tt + t) * HD + d;
                        g_qh[idx] = vh_; g_ql[idx] = vl_;
                    } else if (which == 1) {
                        split_bf16(val, vh_, vl_);
                        size_t idx = ((size_t)bh_i * HD + d) * Tt + t;   // transposed
                        g_kh[idx] = vh_; g_kl[idx] = vl_;
                    } else {
                        split_bf16(val, vh_, vl_);
                        size_t idx = ((size_t)bh_i * Tt + t) * HD + d;
                        g_vh[idx] = vh_; g_vl[idx] = vl_;
                    }
                }
            }
        }
    }
}

// ---------------------------------------------------------------------------
// Tensor-core causal flash attention, bf16x3 (unchanged core from R7).
// Final store -> fp16 hi/lo (feeds fp16 proj GEMM).
// ---------------------------------------------------------------------------
#define FSTR 72
#define FSTAGE 18432

__global__ __launch_bounds__(128, 3) void flash_mma() {
    extern __shared__ __nv_bfloat16 fsm[];
    const int tid = threadIdx.x;
    const int w = tid >> 5, lane = tid & 31;
    const int qb = (int)gridDim.x - 1 - (int)blockIdx.x;
    const int bh = blockIdx.y;
    const int q0 = qb * 64;

    const __nv_bfloat16* Qh_g = g_qh + (size_t)bh * Tt * HD;
    const __nv_bfloat16* Ql_g = g_ql + (size_t)bh * Tt * HD;
    const __nv_bfloat16* Kh_g = g_kh + (size_t)bh * HD * Tt;
    const __nv_bfloat16* Kl_g = g_kl + (size_t)bh * HD * Tt;
    const __nv_bfloat16* Vh_g = g_vh + (size_t)bh * Tt * HD;
    const __nv_bfloat16* Vl_g = g_vl + (size_t)bh * Tt * HD;

    const int laneRowA = (lane & 7) + ((lane >> 3) & 1) * 8;
    const int laneColA = (lane >> 4) * 8;
    const int lb16 = lane & 15;
    const int lbc = (lane >> 4) * 8;

    {
        #pragma unroll
        for (int u = 0; u < 4; u++) {
            int idx = tid + u * 128;
            int r = idx >> 3, c = (idx & 7) * 8;
            cp16(smem_u32(fsm + r * FSTR + c), Qh_g + (size_t)(q0 + r) * HD + c);
            cp16(smem_u32(fsm + 4608 + r * FSTR + c), Ql_g + (size_t)(q0 + r) * HD + c);
        }
        cp_commit();
        cp_wait<0>();
        __syncthreads();
    }
    uint32_t qfh[4][4], qfl[4][4];
    #pragma unroll
    for (int kk = 0; kk < 4; kk++) {
        int r = w * 16 + laneRowA;
        int c = kk * 16 + laneColA;
        ldsm_x4(qfh[kk], smem_u32(fsm + r * FSTR + c));
        ldsm_x4(qfl[kk], smem_u32(fsm + 4608 + r * FSTR + c));
    }
    __syncthreads();

    auto issueKV = [&](int kt, int stage) {
        const int k0 = kt * 64;
        __nv_bfloat16* s = fsm + stage * FSTAGE;
        #pragma unroll
        for (int u = 0; u < 4; u++) {
            int idx = tid + u * 128;
            int r = idx >> 3, c = (idx & 7) * 8;
            cp16(smem_u32(s + r * FSTR + c),          Kh_g + (size_t)r * Tt + k0 + c);
            cp16(smem_u32(s + 4608 + r * FSTR + c),   Kl_g + (size_t)r * Tt + k0 + c);
            cp16(smem_u32(s + 9216 + r * FSTR + c),   Vh_g + (size_t)(k0 + r) * HD + c);
            cp16(smem_u32(s + 13824 + r * FSTR + c),  Vl_g + (size_t)(k0 + r) * HD + c);
        }
        cp_commit();
    };

    float o[8][4] = {};
    float m0 = -1e30f, m1 = -1e30f, l0 = 0.f, l1 = 0.f;
    const int row0g = q0 + w * 16 + (lane >> 2);
    const int row1g = row0g + 8;

    issueKV(0, 0);

    #pragma unroll 1
    for (int kt = 0; kt <= qb; kt++) {
        const int buf = kt & 1;
        if (kt < qb) { issueKV(kt + 1, buf ^ 1); cp_wait<1>(); }
        else         { cp_wait<0>(); }
        __syncthreads();
        __nv_bfloat16* sKh = fsm + buf * FSTAGE;
        __nv_bfloat16* sKl = sKh + 4608;
        __nv_bfloat16* sVh = sKh + 9216;
        __nv_bfloat16* sVl = sKh + 13824;

        float s[8][4] = {};
        #pragma unroll
        for (int kk = 0; kk < 4; kk++) {
            #pragma unroll
            for (int jp = 0; jp < 4; jp++) {
                uint32_t bh4[4], bl4[4];
                uint32_t addr = smem_u32(sKh + (kk * 16 + lb16) * FSTR + jp * 16 + lbc);
                ldsm_x4t(bh4, addr);
                addr = smem_u32(sKl + (kk * 16 + lb16) * FSTR + jp * 16 + lbc);
                ldsm_x4t(bl4, addr);
                #pragma unroll
                for (int h2 = 0; h2 < 2; h2++) {
                    int j = jp * 2 + h2;
                    mma_bf16(s[j], qfh[kk], bh4[2*h2], bh4[2*h2+1]);
                    mma_bf16(s[j], qfh[kk], bl4[2*h2], bl4[2*h2+1]);
                    mma_bf16(s[j], qfl[kk], bh4[2*h2], bh4[2*h2+1]);
                }
            }
        }

        if (kt == qb) {
            const int k0 = kt * 64;
            #pragma unroll
            for (int j = 0; j < 8; j++) {
                int colb = k0 + j * 8 + (lane & 3) * 2;
                if (colb > row0g)     s[j][0] = -1e30f;
                if (colb + 1 > row0g) s[j][1] = -1e30f;
                if (colb > row1g)     s[j][2] = -1e30f;
                if (colb + 1 > row1g) s[j][3] = -1e30f;
            }
        }

        float tmax0 = -1e30f, tmax1 = -1e30f;
        #pragma unroll
        for (int j = 0; j < 8; j++) {
            tmax0 = fmaxf(tmax0, fmaxf(s[j][0], s[j][1]));
            tmax1 = fmaxf(tmax1, fmaxf(s[j][2], s[j][3]));
        }
        tmax0 = fmaxf(tmax0, __shfl_xor_sync(0xffffffffu, tmax0, 1));
        tmax0 = fmaxf(tmax0, __shfl_xor_sync(0xffffffffu, tmax0, 2));
        tmax1 = fmaxf(tmax1, __shfl_xor_sync(0xffffffffu, tmax1, 1));
        tmax1 = fmaxf(tmax1, __shfl_xor_sync(0xffffffffu, tmax1, 2));
        float mn0 = fmaxf(m0, tmax0), mn1 = fmaxf(m1, tmax1);
        float al0 = __expf(m0 - mn0), al1 = __expf(m1 - mn1);
        m0 = mn0; m1 = mn1;
        float ps0 = 0.f, ps1 = 0.f;
        #pragma unroll
        for (int j = 0; j < 8; j++) {
            s[j][0] = __expf(s[j][0] - mn0);
            s[j][1] = __expf(s[j][1] - mn0);
            s[j][2] = __expf(s[j][2] - mn1);
            s[j][3] = __expf(s[j][3] - mn1);
            ps0 += s[j][0] + s[j][1];
            ps1 += s[j][2] + s[j][3];
        }
        l0 = l0 * al0 + ps0;
        l1 = l1 * al1 + ps1;
        #pragma unroll
        for (int j = 0; j < 8; j++) {
            o[j][0] *= al0; o[j][1] *= al0;
            o[j][2] *= al1; o[j][3] *= al1;
        }

        #pragma unroll
        for (int kk = 0; kk < 4; kk++) {
            uint32_t aph[4], apl[4];
            {
                float x0 = s[2*kk][0],   x1 = s[2*kk][1];
                float x2 = s[2*kk][2],   x3 = s[2*kk][3];
                float y0 = s[2*kk+1][0], y1 = s[2*kk+1][1];
                float y2 = s[2*kk+1][2], y3 = s[2*kk+1][3];
                aph[0] = pack_bf2(x0, x1);
                aph[1] = pack_bf2(x2, x3);
                aph[2] = pack_bf2(y0, y1);
                aph[3] = pack_bf2(y2, y3);
                apl[0] = pack_bf2(x0 - __bfloat162float(__float2bfloat16(x0)),
                                  x1 - __bfloat162float(__float2bfloat16(x1)));
                apl[1] = pack_bf2(x2 - __bfloat162float(__float2bfloat16(x2)),
                                  x3 - __bfloat162float(__float2bfloat16(x3)));
                apl[2] = pack_bf2(y0 - __bfloat162float(__float2bfloat16(y0)),
                                  y1 - __bfloat162float(__float2bfloat16(y1)));
                apl[3] = pack_bf2(y2 - __bfloat162float(__float2bfloat16(y2)),
                                  y3 - __bfloat162float(__float2bfloat16(y3)));
            }
            #pragma unroll
            for (int jp = 0; jp < 4; jp++) {
                uint32_t vh4[4], vl4[4];
                uint32_t addr = smem_u32(sVh + (kk * 16 + lb16) * FSTR + jp * 16 + lbc);
                ldsm_x4t(vh4, addr);
                addr = smem_u32(sVl + (kk * 16 + lb16) * FSTR + jp * 16 + lbc);
                ldsm_x4t(vl4, addr);
                #pragma unroll
                for (int h2 = 0; h2 < 2; h2++) {
                    int j = jp * 2 + h2;
                    mma_bf16(o[j], aph, vh4[2*h2], vh4[2*h2+1]);
                    mma_bf16(o[j], aph, vl4[2*h2], vl4[2*h2+1]);
                    mma_bf16(o[j], apl, vh4[2*h2], vh4[2*h2+1]);
                }
            }
        }
        __syncthreads();
    }

    l0 += __shfl_xor_sync(0xffffffffu, l0, 1);
    l0 += __shfl_xor_sync(0xffffffffu, l0, 2);
    l1 += __shfl_xor_sync(0xffffffffu, l1, 1);
    l1 += __shfl_xor_sync(0xffffffffu, l1, 2);
    float inv0 = 1.f / l0, inv1 = 1.f / l1;

    const int b = bh >> 4, h = bh & 15;
    #pragma unroll
    for (int j = 0; j < 8; j++) {
        int col = h * HD + j * 8 + (lane & 3) * 2;
        {
            float v0 = o[j][0] * inv0, v1 = o[j][1] * inv0;
            size_t idx = ((size_t)(b * Tt + row0g)) * Cc + col;
            *reinterpret_cast<__half2*>(&g_atth[idx]) = __floats2half2_rn(v0, v1);
            float lv0 = v0 - __half2float(__float2half_rn(v0));
            float lv1 = v1 - __half2float(__float2half_rn(v1));
            *reinterpret_cast<__half2*>(&g_attl[idx]) = __floats2half2_rn(lv0, lv1);
        }
        {
            float v0 = o[j][2] * inv1, v1 = o[j][3] * inv1;
            size_t idx = ((size_t)(b * Tt + row1g)) * Cc + col;
            *reinterpret_cast<__half2*>(&g_atth[idx]) = __floats2half2_rn(v0, v1);
            float lv0 = v0 - __half2float(__float2half_rn(v0));
            float lv1 = v1 - __half2float(__float2half_rn(v1));
            *reinterpret_cast<__half2*>(&g_attl[idx]) = __floats2half2_rn(lv0, lv1);
        }
    }
}

// ---------------------------------------------------------------------------
extern "C" void kernel_launch(void* const* d_in, const int* in_sizes, int n_in,
                              void* d_out, int out_size) {
    const float* x        = (const float*)d_in[0];
    const float* ln_scale = (const float*)d_in[2];
    const float* ln_bias  = (const float*)d_in[3];
    const float* qkv_w    = (const float*)d_in[4];
    const float* qkv_b    = (const float*)d_in[5];
    const float* proj_w   = (const float*)d_in[6];
    const float* proj_b   = (const float*)d_in[7];
    float* out = (float*)d_out;

    const int gemm_smem  = STAGE_E * 2 * (int)sizeof(__half);          // 58368
    const int flash_smem = FSTAGE * 2 * (int)sizeof(__nv_bfloat16);    // 73728

    static bool attr_set = false;
    if (!attr_set) {
        cudaFuncSetAttribute(flash_mma,
                             cudaFuncAttributeMaxDynamicSharedMemorySize, flash_smem);
        cudaFuncSetAttribute(mma_gemm<QKV_N, 0>,
                             cudaFuncAttributeMaxDynamicSharedMemorySize, gemm_smem);
        cudaFuncSetAttribute(mma_gemm<Cc, 1>,
                             cudaFuncAttributeMaxDynamicSharedMemorySize, gemm_smem);
        attr_set = true;
    }

    __half *xnh, *xnl, *wq, *wp, *atth, *attl;
    cudaGetSymbolAddress((void**)&xnh, g_xnh);
    cudaGetSymbolAddress((void**)&xnl, g_xnl);
    cudaGetSymbolAddress((void**)&wq, g_wq);
    cudaGetSymbolAddress((void**)&wp, g_wp);
    cudaGetSymbolAddress((void**)&atth, g_atth);
    cudaGetSymbolAddress((void**)&attl, g_attl);

    ln_kernel<<<MROWS, 256>>>(x, ln_scale, ln_bias);
    cvt_kernel<<<(Cc * QKV_N) / 1024, 256>>>(qkv_w, wq);
    cvt_kernel<<<(Cc * Cc) / 1024, 256>>>(proj_w, wp);

    mma_gemm<QKV_N, 0><<<dim3(QKV_N / 128, MROWS / 128), 256, gemm_smem>>>(
        xnh, xnl, wq, qkv_b, nullptr);
    flash_mma<<<dim3(Tt / 64, Bb * NH), 128, flash_smem>>>();
    mma_gemm<Cc, 1><<<dim3(Cc / 128, MROWS / 128), 256, gemm_smem>>>(
        atth, attl, wp, proj_b, out);
}

// round 9
// speedup vs baseline: 4.5588x; 1.2853x over previous
#include <cuda_runtime.h>
#include <cuda_bf16.h>
#include <cuda_fp16.h>
#include <cstdint>
#include <math.h>

#define Bb 2
#define Tt 2048
#define Cc 1024
#define NH 16
#define HD 64
#define MROWS (Bb*Tt)          // 4096
#define QKV_N (3*Cc)           // 3072

// Scratch
__device__ __half g_xnh [MROWS*Cc];            // LN out hi (fp16)
__device__ __half g_xnl [MROWS*Cc];            // LN out lo (fp16)
__device__ __half g_wq  [Cc*QKV_N];            // qkv W single fp16
__device__ __half g_wp  [Cc*Cc];               // proj W single fp16
__device__ __half g_qh [Bb*NH*Tt*HD];          // [b,h,t,d] hi (scaled 1/8)
__device__ __half g_ql [Bb*NH*Tt*HD];          // [b,h,t,d] lo
__device__ __half g_k  [Bb*NH*HD*Tt];          // [b,h,d,t] single (transposed)
__device__ __half g_v  [Bb*NH*Tt*HD];          // [b,h,t,d] single
__device__ __half g_atth[MROWS*Cc];            // attention out hi (fp16)
__device__ __half g_attl[MROWS*Cc];            // attention out lo (fp16)

__device__ __forceinline__ uint32_t smem_u32(const void* p) {
    return (uint32_t)__cvta_generic_to_shared(p);
}
__device__ __forceinline__ void cp16(uint32_t dst, const void* src) {
    asm volatile("cp.async.ca.shared.global [%0], [%1], 16;\n" :: "r"(dst), "l"(src));
}
__device__ __forceinline__ void cp_commit() { asm volatile("cp.async.commit_group;\n"); }
template<int N> __device__ __forceinline__ void cp_wait() {
    asm volatile("cp.async.wait_group %0;\n" :: "n"(N));
}
__device__ __forceinline__ void ldsm_x4(uint32_t a[4], uint32_t addr) {
    asm volatile("ldmatrix.sync.aligned.m8n8.x4.shared.b16 {%0,%1,%2,%3}, [%4];"
                 : "=r"(a[0]),"=r"(a[1]),"=r"(a[2]),"=r"(a[3]) : "r"(addr));
}
__device__ __forceinline__ void ldsm_x2t(uint32_t b[2], uint32_t addr) {
    asm volatile("ldmatrix.sync.aligned.m8n8.x2.trans.shared.b16 {%0,%1}, [%2];"
                 : "=r"(b[0]),"=r"(b[1]) : "r"(addr));
}
__device__ __forceinline__ void ldsm_x4t(uint32_t b[4], uint32_t addr) {
    asm volatile("ldmatrix.sync.aligned.m8n8.x4.trans.shared.b16 {%0,%1,%2,%3}, [%4];"
                 : "=r"(b[0]),"=r"(b[1]),"=r"(b[2]),"=r"(b[3]) : "r"(addr));
}
__device__ __forceinline__ void mma_f16(float c[4], const uint32_t a[4], const uint32_t b0, const uint32_t b1) {
    asm volatile("mma.sync.aligned.m16n8k16.row.col.f32.f16.f16.f32 "
        "{%0,%1,%2,%3}, {%4,%5,%6,%7}, {%8,%9}, {%0,%1,%2,%3};"
        : "+f"(c[0]),"+f"(c[1]),"+f"(c[2]),"+f"(c[3])
        : "r"(a[0]),"r"(a[1]),"r"(a[2]),"r"(a[3]), "r"(b0),"r"(b1));
}
__device__ __forceinline__ void split_fp16(float v, __half& h, __half& l) {
    h = __float2half_rn(v);
    l = __float2half_rn(v - __half2float(h));
}
__device__ __forceinline__ uint32_t pack_hf2(float x, float y) {
    __half2 t = __floats2half2_rn(x, y);
    return *reinterpret_cast<uint32_t*>(&t);
}

// ---------------------------------------------------------------------------
// LayerNorm -> fp16 hi/lo
// ---------------------------------------------------------------------------
__device__ __forceinline__ float block_sum256(float v, float* red) {
    #pragma unroll
    for (int o = 16; o > 0; o >>= 1) v += __shfl_xor_sync(0xffffffffu, v, o);
    int w = threadIdx.x >> 5;
    if ((threadIdx.x & 31) == 0) red[w] = v;
    __syncthreads();
    float t = (threadIdx.x < 8) ? red[threadIdx.x] : 0.f;
    if (threadIdx.x < 32) {
        #pragma unroll
        for (int o = 4; o > 0; o >>= 1) t += __shfl_xor_sync(0xffffffffu, t, o);
        if (threadIdx.x == 0) red[0] = t;
    }
    __syncthreads();
    float r = red[0];
    __syncthreads();
    return r;
}

__global__ __launch_bounds__(256) void ln_kernel(
    const float* __restrict__ x, const float* __restrict__ scale,
    const float* __restrict__ bias) {
    __shared__ float red[8];
    const int row = blockIdx.x;
    const int tid = threadIdx.x;
    float4 v = reinterpret_cast<const float4*>(x + (size_t)row * Cc)[tid];
    float s = v.x + v.y + v.z + v.w;
    float mu = block_sum256(s, red) * (1.f / Cc);
    float dx = v.x - mu, dy = v.y - mu, dz = v.z - mu, dw = v.w - mu;
    float sq = dx*dx + dy*dy + dz*dz + dw*dw;
    float var = block_sum256(sq, red) * (1.f / Cc);
    float inv = rsqrtf(var + 1e-6f);
    float4 sc = reinterpret_cast<const float4*>(scale)[tid];
    float4 bi = reinterpret_cast<const float4*>(bias)[tid];
    float o[4];
    o[0] = dx * inv * sc.x + bi.x;
    o[1] = dy * inv * sc.y + bi.y;
    o[2] = dz * inv * sc.z + bi.z;
    o[3] = dw * inv * sc.w + bi.w;
    size_t base = (size_t)row * Cc + tid * 4;
    #pragma unroll
    for (int e = 0; e < 4; e++) {
        __half h, l;
        split_fp16(o[e], h, l);
        g_xnh[base + e] = h;
        g_xnl[base + e] = l;
    }
}

// ---------------------------------------------------------------------------
// fp32 -> fp16 single (weights)
// ---------------------------------------------------------------------------
__global__ __launch_bounds__(256) void cvt_kernel(
    const float* __restrict__ src, __half* __restrict__ dst) {
    int i = (blockIdx.x * 256 + threadIdx.x) * 4;
    float4 v = *reinterpret_cast<const float4*>(src + i);
    *reinterpret_cast<__half2*>(&dst[i])     = __floats2half2_rn(v.x, v.y);
    *reinterpret_cast<__half2*>(&dst[i + 2]) = __floats2half2_rn(v.z, v.w);
}

// ---------------------------------------------------------------------------
// fp16 2-term tensor-core GEMM: 128x128 block, 8 warps (2x4), warp tile 64x32.
// ---------------------------------------------------------------------------
#define STAGE_E 14592
#define A_STR 40
#define B_STR 136

template<int ND, int EPI>
__global__ __launch_bounds__(256, 2) void mma_gemm(
    const __half* __restrict__ Ah_g, const __half* __restrict__ Al_g,
    const __half* __restrict__ B_g,
    const float* __restrict__ bias, float* __restrict__ Cout)
{
    extern __shared__ __half smem[];
    const int tid = threadIdx.x;
    const int wid = tid >> 5, lane = tid & 31;
    const int wm = wid >> 2, wn = wid & 3;
    const int row0 = blockIdx.y * 128;
    const int col0 = blockIdx.x * 128;

    const int laneRowA = (lane & 7) + ((lane >> 3) & 1) * 8;
    const int laneColA = (lane >> 4) * 8;
    const int laneB = lane & 15;

    auto issue = [&](int it, int stage) {
        const int k0 = it * 32;
        __half* s = smem + stage * STAGE_E;
        #pragma unroll
        for (int u = 0; u < 2; u++) {
            int c = tid + u * 256;
            int ar = c >> 2, ac = (c & 3) * 8;
            cp16(smem_u32(s + ar * A_STR + ac),
                 Ah_g + (size_t)(row0 + ar) * Cc + k0 + ac);
            cp16(smem_u32(s + 5120 + ar * A_STR + ac),
                 Al_g + (size_t)(row0 + ar) * Cc + k0 + ac);
            int br = c >> 4, bc = (c & 15) * 8;
            cp16(smem_u32(s + 10240 + br * B_STR + bc),
                 B_g + (size_t)(k0 + br) * ND + col0 + bc);
        }
        cp_commit();
    };

    float acc[4][4][4] = {};
    issue(0, 0);

    #pragma unroll 1
    for (int it = 0; it < 32; it++) {
        const int buf = it & 1;
        if (it + 1 < 32) { issue(it + 1, buf ^ 1); cp_wait<1>(); }
        else             { cp_wait<0>(); }
        __syncthreads();
        __half* sAh = smem + buf * STAGE_E;
        __half* sAl = sAh + 5120;
        __half* sB  = sAh + 10240;
        #pragma unroll
        for (int kk = 0; kk < 2; kk++) {
            uint32_t ah[4][4], al[4][4], bb[4][2];
            #pragma unroll
            for (int i = 0; i < 4; i++) {
                int r = wm * 64 + i * 16 + laneRowA;
                int cA = kk * 16 + laneColA;
                ldsm_x4(ah[i], smem_u32(sAh + r * A_STR + cA));
                ldsm_x4(al[i], smem_u32(sAl + r * A_STR + cA));
            }
            #pragma unroll
            for (int j = 0; j < 4; j++) {
                int rB = kk * 16 + laneB;
                int cB = wn * 32 + j * 8;
                ldsm_x2t(bb[j], smem_u32(sB + rB * B_STR + cB));
            }
            #pragma unroll
            for (int i = 0; i < 4; i++)
                #pragma unroll
                for (int j = 0; j < 4; j++) {
                    mma_f16(acc[i][j], ah[i], bb[j][0], bb[j][1]);
                    mma_f16(acc[i][j], al[i], bb[j][0], bb[j][1]);
                }
        }
        __syncthreads();
    }

    // Epilogue
    #pragma unroll
    for (int i = 0; i < 4; i++) {
        int rbase = row0 + wm * 64 + i * 16 + (lane >> 2);
        #pragma unroll
        for (int j = 0; j < 4; j++) {
            int nb = col0 + wn * 32 + j * 8 + (lane & 3) * 2;
            #pragma unroll
            for (int e = 0; e < 4; e++) {
                int m = rbase + (e >> 1) * 8;
                int n = nb + (e & 1);
                float val = acc[i][j][e] + bias[n];
                if (EPI == 1) {
                    Cout[(size_t)m * Cc + n] = val;
                } else {
                    int b = m >> 11, t = m & 2047;
                    int which = n >> 10, rr = n & 1023;
                    int h = rr >> 6, d = rr & 63;
                    int bh_i = b * NH + h;
                    if (which == 0) {
                        __half vh_, vl_;
                        split_fp16(val * 0.125f, vh_, vl_);
                        size_t idx = ((size_t)bh_i * Tt + t) * HD + d;
                        g_qh[idx] = vh_; g_ql[idx] = vl_;
                    } else if (which == 1) {
                        size_t idx = ((size_t)bh_i * HD + d) * Tt + t;   // transposed
                        g_k[idx] = __float2half_rn(val);
                    } else {
                        size_t idx = ((size_t)bh_i * Tt + t) * HD + d;
                        g_v[idx] = __float2half_rn(val);
                    }
                }
            }
        }
    }
}

// ---------------------------------------------------------------------------
// Tensor-core causal flash attention, fp16 thin:
//   S  = Qh*K + Ql*K   (Q split fp16, K single fp16)   — 2 MMA
//   PV = P*V           (P, V single fp16)              — 1 MMA
// KV stage: K[64][72] + V[64][72] fp16 = 9216 elems (18KB); 2 stages.
// ---------------------------------------------------------------------------
#define FSTR 72
#define FSTAGE 9216

__global__ __launch_bounds__(128, 4) void flash_mma() {
    extern __shared__ __half fsm[];
    const int tid = threadIdx.x;
    const int w = tid >> 5, lane = tid & 31;
    const int qb = (int)gridDim.x - 1 - (int)blockIdx.x;
    const int bh = blockIdx.y;
    const int q0 = qb * 64;

    const __half* Qh_g = g_qh + (size_t)bh * Tt * HD;
    const __half* Ql_g = g_ql + (size_t)bh * Tt * HD;
    const __half* K_g  = g_k  + (size_t)bh * HD * Tt;
    const __half* V_g  = g_v  + (size_t)bh * Tt * HD;

    const int laneRowA = (lane & 7) + ((lane >> 3) & 1) * 8;
    const int laneColA = (lane >> 4) * 8;
    const int lb16 = lane & 15;
    const int lbc = (lane >> 4) * 8;

    // stage Q (hi at 0, lo at 4608) through stage-0 smem, extract fragments
    {
        #pragma unroll
        for (int u = 0; u < 4; u++) {
            int idx = tid + u * 128;
            int r = idx >> 3, c = (idx & 7) * 8;
            cp16(smem_u32(fsm + r * FSTR + c), Qh_g + (size_t)(q0 + r) * HD + c);
            cp16(smem_u32(fsm + 4608 + r * FSTR + c), Ql_g + (size_t)(q0 + r) * HD + c);
        }
        cp_commit();
        cp_wait<0>();
        __syncthreads();
    }
    uint32_t qfh[4][4], qfl[4][4];
    #pragma unroll
    for (int kk = 0; kk < 4; kk++) {
        int r = w * 16 + laneRowA;
        int c = kk * 16 + laneColA;
        ldsm_x4(qfh[kk], smem_u32(fsm + r * FSTR + c));
        ldsm_x4(qfl[kk], smem_u32(fsm + 4608 + r * FSTR + c));
    }
    __syncthreads();

    auto issueKV = [&](int kt, int stage) {
        const int k0 = kt * 64;
        __half* s = fsm + stage * FSTAGE;
        #pragma unroll
        for (int u = 0; u < 4; u++) {
            int idx = tid + u * 128;
            int r = idx >> 3, c = (idx & 7) * 8;
            cp16(smem_u32(s + r * FSTR + c),        K_g + (size_t)r * Tt + k0 + c);
            cp16(smem_u32(s + 4608 + r * FSTR + c), V_g + (size_t)(k0 + r) * HD + c);
        }
        cp_commit();
    };

    float o[8][4] = {};
    float m0 = -1e30f, m1 = -1e30f, l0 = 0.f, l1 = 0.f;
    const int row0g = q0 + w * 16 + (lane >> 2);
    const int row1g = row0g + 8;

    issueKV(0, 0);

    #pragma unroll 1
    for (int kt = 0; kt <= qb; kt++) {
        const int buf = kt & 1;
        if (kt < qb) { issueKV(kt + 1, buf ^ 1); cp_wait<1>(); }
        else         { cp_wait<0>(); }
        __syncthreads();
        __half* sK = fsm + buf * FSTAGE;
        __half* sV = sK + 4608;

        // ---- S = Qh K + Ql K ----
        float s[8][4] = {};
        #pragma unroll
        for (int kk = 0; kk < 4; kk++) {
            #pragma unroll
            for (int jp = 0; jp < 4; jp++) {
                uint32_t kb[4];
                ldsm_x4t(kb, smem_u32(sK + (kk * 16 + lb16) * FSTR + jp * 16 + lbc));
                #pragma unroll
                for (int h2 = 0; h2 < 2; h2++) {
                    int j = jp * 2 + h2;
                    mma_f16(s[j], qfh[kk], kb[2*h2], kb[2*h2+1]);
                    mma_f16(s[j], qfl[kk], kb[2*h2], kb[2*h2+1]);
                }
            }
        }

        if (kt == qb) {
            const int k0 = kt * 64;
            #pragma unroll
            for (int j = 0; j < 8; j++) {
                int colb = k0 + j * 8 + (lane & 3) * 2;
                if (colb > row0g)     s[j][0] = -1e30f;
                if (colb + 1 > row0g) s[j][1] = -1e30f;
                if (colb > row1g)     s[j][2] = -1e30f;
                if (colb + 1 > row1g) s[j][3] = -1e30f;
            }
        }

        // ---- online softmax ----
        float tmax0 = -1e30f, tmax1 = -1e30f;
        #pragma unroll
        for (int j = 0; j < 8; j++) {
            tmax0 = fmaxf(tmax0, fmaxf(s[j][0], s[j][1]));
            tmax1 = fmaxf(tmax1, fmaxf(s[j][2], s[j][3]));
        }
        tmax0 = fmaxf(tmax0, __shfl_xor_sync(0xffffffffu, tmax0, 1));
        tmax0 = fmaxf(tmax0, __shfl_xor_sync(0xffffffffu, tmax0, 2));
        tmax1 = fmaxf(tmax1, __shfl_xor_sync(0xffffffffu, tmax1, 1));
        tmax1 = fmaxf(tmax1, __shfl_xor_sync(0xffffffffu, tmax1, 2));
        float mn0 = fmaxf(m0, tmax0), mn1 = fmaxf(m1, tmax1);
        float al0 = __expf(m0 - mn0), al1 = __expf(m1 - mn1);
        m0 = mn0; m1 = mn1;
        float ps0 = 0.f, ps1 = 0.f;
        #pragma unroll
        for (int j = 0; j < 8; j++) {
            s[j][0] = __expf(s[j][0] - mn0);
            s[j][1] = __expf(s[j][1] - mn0);
            s[j][2] = __expf(s[j][2] - mn1);
            s[j][3] = __expf(s[j][3] - mn1);
            ps0 += s[j][0] + s[j][1];
            ps1 += s[j][2] + s[j][3];
        }
        l0 = l0 * al0 + ps0;
        l1 = l1 * al1 + ps1;
        #pragma unroll
        for (int j = 0; j < 8; j++) {
            o[j][0] *= al0; o[j][1] *= al0;
            o[j][2] *= al1; o[j][3] *= al1;
        }

        // ---- O += P V (single fp16 each) ----
        #pragma unroll
        for (int kk = 0; kk < 4; kk++) {
            uint32_t ap[4];
            ap[0] = pack_hf2(s[2*kk][0],   s[2*kk][1]);
            ap[1] = pack_hf2(s[2*kk][2],   s[2*kk][3]);
            ap[2] = pack_hf2(s[2*kk+1][0], s[2*kk+1][1]);
            ap[3] = pack_hf2(s[2*kk+1][2], s[2*kk+1][3]);
            #pragma unroll
            for (int jp = 0; jp < 4; jp++) {
                uint32_t vb[4];
                ldsm_x4t(vb, smem_u32(sV + (kk * 16 + lb16) * FSTR + jp * 16 + lbc));
                #pragma unroll
                for (int h2 = 0; h2 < 2; h2++) {
                    int j = jp * 2 + h2;
                    mma_f16(o[j], ap, vb[2*h2], vb[2*h2+1]);
                }
            }
        }
        __syncthreads();
    }

    l0 += __shfl_xor_sync(0xffffffffu, l0, 1);
    l0 += __shfl_xor_sync(0xffffffffu, l0, 2);
    l1 += __shfl_xor_sync(0xffffffffu, l1, 1);
    l1 += __shfl_xor_sync(0xffffffffu, l1, 2);
    float inv0 = 1.f / l0, inv1 = 1.f / l1;

    const int b = bh >> 4, h = bh & 15;
    #pragma unroll
    for (int j = 0; j < 8; j++) {
        int col = h * HD + j * 8 + (lane & 3) * 2;
        {
            float v0 = o[j][0] * inv0, v1 = o[j][1] * inv0;
            size_t idx = ((size_t)(b * Tt + row0g)) * Cc + col;
            *reinterpret_cast<__half2*>(&g_atth[idx]) = __floats2half2_rn(v0, v1);
            float lv0 = v0 - __half2float(__float2half_rn(v0));
            float lv1 = v1 - __half2float(__float2half_rn(v1));
            *reinterpret_cast<__half2*>(&g_attl[idx]) = __floats2half2_rn(lv0, lv1);
        }
        {
            float v0 = o[j][2] * inv1, v1 = o[j][3] * inv1;
            size_t idx = ((size_t)(b * Tt + row1g)) * Cc + col;
            *reinterpret_cast<__half2*>(&g_atth[idx]) = __floats2half2_rn(v0, v1);
            float lv0 = v0 - __half2float(__float2half_rn(v0));
            float lv1 = v1 - __half2float(__float2half_rn(v1));
            *reinterpret_cast<__half2*>(&g_attl[idx]) = __floats2half2_rn(lv0, lv1);
        }
    }
}

// ---------------------------------------------------------------------------
extern "C" void kernel_launch(void* const* d_in, const int* in_sizes, int n_in,
                              void* d_out, int out_size) {
    const float* x        = (const float*)d_in[0];
    const float* ln_scale = (const float*)d_in[2];
    const float* ln_bias  = (const float*)d_in[3];
    const float* qkv_w    = (const float*)d_in[4];
    const float* qkv_b    = (const float*)d_in[5];
    const float* proj_w   = (const float*)d_in[6];
    const float* proj_b   = (const float*)d_in[7];
    float* out = (float*)d_out;

    const int gemm_smem  = STAGE_E * 2 * (int)sizeof(__half);   // 58368
    const int flash_smem = FSTAGE * 2 * (int)sizeof(__half);    // 36864

    static bool attr_set = false;
    if (!attr_set) {
        cudaFuncSetAttribute(flash_mma,
                             cudaFuncAttributeMaxDynamicSharedMemorySize, flash_smem);
        cudaFuncSetAttribute(mma_gemm<QKV_N, 0>,
                             cudaFuncAttributeMaxDynamicSharedMemorySize, gemm_smem);
        cudaFuncSetAttribute(mma_gemm<Cc, 1>,
                             cudaFuncAttributeMaxDynamicSharedMemorySize, gemm_smem);
        attr_set = true;
    }

    __half *xnh, *xnl, *wq, *wp, *atth, *attl;
    cudaGetSymbolAddress((void**)&xnh, g_xnh);
    cudaGetSymbolAddress((void**)&xnl, g_xnl);
    cudaGetSymbolAddress((void**)&wq, g_wq);
    cudaGetSymbolAddress((void**)&wp, g_wp);
    cudaGetSymbolAddress((void**)&atth, g_atth);
    cudaGetSymbolAddress((void**)&attl, g_attl);

    ln_kernel<<<MROWS, 256>>>(x, ln_scale, ln_bias);
    cvt_kernel<<<(Cc * QKV_N) / 1024, 256>>>(qkv_w, wq);
    cvt_kernel<<<(Cc * Cc) / 1024, 256>>>(proj_w, wp);

    mma_gemm<QKV_N, 0><<<dim3(QKV_N / 128, MROWS / 128), 256, gemm_smem>>>(
        xnh, xnl, wq, qkv_b, nullptr);
    flash_mma<<<dim3(Tt / 64, Bb * NH), 128, flash_smem>>>();
    mma_gemm<Cc, 1><<<dim3(Cc / 128, MROWS / 128), 256, gemm_smem>>>(
        atth, attl, wp, proj_b, out);
}

// round 10
// speedup vs baseline: 6.3527x; 1.3935x over previous
#include <cuda_runtime.h>
#include <cuda_bf16.h>
#include <cuda_fp16.h>
#include <cstdint>
#include <math.h>

#define Bb 2
#define Tt 2048
#define Cc 1024
#define NH 16
#define HD 64
#define MROWS (Bb*Tt)          // 4096
#define QKV_N (3*Cc)           // 3072

// Scratch
__device__ __half g_xn  [MROWS*Cc];            // LN out single fp16
__device__ __half g_wq  [Cc*QKV_N];            // qkv W single fp16
__device__ __half g_wp  [Cc*Cc];               // proj W single fp16
__device__ __half g_qh [Bb*NH*Tt*HD];          // [b,h,t,d] hi (scaled 1/8)
__device__ __half g_ql [Bb*NH*Tt*HD];          // [b,h,t,d] lo
__device__ __half g_k  [Bb*NH*HD*Tt];          // [b,h,d,t] single (transposed)
__device__ __half g_v  [Bb*NH*Tt*HD];          // [b,h,t,d] single
__device__ __half g_att[MROWS*Cc];             // attention out single fp16

__device__ __forceinline__ uint32_t smem_u32(const void* p) {
    return (uint32_t)__cvta_generic_to_shared(p);
}
__device__ __forceinline__ void cp16(uint32_t dst, const void* src) {
    asm volatile("cp.async.ca.shared.global [%0], [%1], 16;\n" :: "r"(dst), "l"(src));
}
__device__ __forceinline__ void cp_commit() { asm volatile("cp.async.commit_group;\n"); }
template<int N> __device__ __forceinline__ void cp_wait() {
    asm volatile("cp.async.wait_group %0;\n" :: "n"(N));
}
__device__ __forceinline__ void ldsm_x4(uint32_t a[4], uint32_t addr) {
    asm volatile("ldmatrix.sync.aligned.m8n8.x4.shared.b16 {%0,%1,%2,%3}, [%4];"
                 : "=r"(a[0]),"=r"(a[1]),"=r"(a[2]),"=r"(a[3]) : "r"(addr));
}
__device__ __forceinline__ void ldsm_x2t(uint32_t b[2], uint32_t addr) {
    asm volatile("ldmatrix.sync.aligned.m8n8.x2.trans.shared.b16 {%0,%1}, [%2];"
                 : "=r"(b[0]),"=r"(b[1]) : "r"(addr));
}
__device__ __forceinline__ void ldsm_x4t(uint32_t b[4], uint32_t addr) {
    asm volatile("ldmatrix.sync.aligned.m8n8.x4.trans.shared.b16 {%0,%1,%2,%3}, [%4];"
                 : "=r"(b[0]),"=r"(b[1]),"=r"(b[2]),"=r"(b[3]) : "r"(addr));
}
__device__ __forceinline__ void mma_f16(float c[4], const uint32_t a[4], const uint32_t b0, const uint32_t b1) {
    asm volatile("mma.sync.aligned.m16n8k16.row.col.f32.f16.f16.f32 "
        "{%0,%1,%2,%3}, {%4,%5,%6,%7}, {%8,%9}, {%0,%1,%2,%3};"
        : "+f"(c[0]),"+f"(c[1]),"+f"(c[2]),"+f"(c[3])
        : "r"(a[0]),"r"(a[1]),"r"(a[2]),"r"(a[3]), "r"(b0),"r"(b1));
}
__device__ __forceinline__ void split_fp16(float v, __half& h, __half& l) {
    h = __float2half_rn(v);
    l = __float2half_rn(v - __half2float(h));
}
__device__ __forceinline__ uint32_t pack_hf2(float x, float y) {
    __half2 t = __floats2half2_rn(x, y);
    return *reinterpret_cast<uint32_t*>(&t);
}

// ---------------------------------------------------------------------------
// LayerNorm -> single fp16
// ---------------------------------------------------------------------------
__device__ __forceinline__ float block_sum256(float v, float* red) {
    #pragma unroll
    for (int o = 16; o > 0; o >>= 1) v += __shfl_xor_sync(0xffffffffu, v, o);
    int w = threadIdx.x >> 5;
    if ((threadIdx.x & 31) == 0) red[w] = v;
    __syncthreads();
    float t = (threadIdx.x < 8) ? red[threadIdx.x] : 0.f;
    if (threadIdx.x < 32) {
        #pragma unroll
        for (int o = 4; o > 0; o >>= 1) t += __shfl_xor_sync(0xffffffffu, t, o);
        if (threadIdx.x == 0) red[0] = t;
    }
    __syncthreads();
    float r = red[0];
    __syncthreads();
    return r;
}

__global__ __launch_bounds__(256) void ln_kernel(
    const float* __restrict__ x, const float* __restrict__ scale,
    const float* __restrict__ bias) {
    __shared__ float red[8];
    const int row = blockIdx.x;
    const int tid = threadIdx.x;
    float4 v = reinterpret_cast<const float4*>(x + (size_t)row * Cc)[tid];
    float s = v.x + v.y + v.z + v.w;
    float mu = block_sum256(s, red) * (1.f / Cc);
    float dx = v.x - mu, dy = v.y - mu, dz = v.z - mu, dw = v.w - mu;
    float sq = dx*dx + dy*dy + dz*dz + dw*dw;
    float var = block_sum256(sq, red) * (1.f / Cc);
    float inv = rsqrtf(var + 1e-6f);
    float4 sc = reinterpret_cast<const float4*>(scale)[tid];
    float4 bi = reinterpret_cast<const float4*>(bias)[tid];
    size_t base = (size_t)row * Cc + tid * 4;
    *reinterpret_cast<__half2*>(&g_xn[base]) =
        __floats2half2_rn(dx * inv * sc.x + bi.x, dy * inv * sc.y + bi.y);
    *reinterpret_cast<__half2*>(&g_xn[base + 2]) =
        __floats2half2_rn(dz * inv * sc.z + bi.z, dw * inv * sc.w + bi.w);
}

// ---------------------------------------------------------------------------
// fp32 -> fp16 single (weights)
// ---------------------------------------------------------------------------
__global__ __launch_bounds__(256) void cvt_kernel(
    const float* __restrict__ src, __half* __restrict__ dst) {
    int i = (blockIdx.x * 256 + threadIdx.x) * 4;
    float4 v = *reinterpret_cast<const float4*>(src + i);
    *reinterpret_cast<__half2*>(&dst[i])     = __floats2half2_rn(v.x, v.y);
    *reinterpret_cast<__half2*>(&dst[i + 2]) = __floats2half2_rn(v.z, v.w);
}

// ---------------------------------------------------------------------------
// fp16 single tensor-core GEMM: 128x128 block, 8 warps (2x4), warp tile 64x32.
// C = A*B, fp32 accum. Stage: A[128][40]=5120 + B[32][136]=4352 = 9472 elems.
// ---------------------------------------------------------------------------
#define STAGE_E 9472
#define A_STR 40
#define B_STR 136

template<int ND, int EPI>
__global__ __launch_bounds__(256, 2) void mma_gemm(
    const __half* __restrict__ A_g, const __half* __restrict__ B_g,
    const float* __restrict__ bias, float* __restrict__ Cout)
{
    extern __shared__ __half smem[];
    const int tid = threadIdx.x;
    const int wid = tid >> 5, lane = tid & 31;
    const int wm = wid >> 2, wn = wid & 3;
    const int row0 = blockIdx.y * 128;
    const int col0 = blockIdx.x * 128;

    const int laneRowA = (lane & 7) + ((lane >> 3) & 1) * 8;
    const int laneColA = (lane >> 4) * 8;
    const int laneB = lane & 15;

    auto issue = [&](int it, int stage) {
        const int k0 = it * 32;
        __half* s = smem + stage * STAGE_E;
        #pragma unroll
        for (int u = 0; u < 2; u++) {
            int c = tid + u * 256;
            int ar = c >> 2, ac = (c & 3) * 8;
            cp16(smem_u32(s + ar * A_STR + ac),
                 A_g + (size_t)(row0 + ar) * Cc + k0 + ac);
            int br = c >> 4, bc = (c & 15) * 8;
            cp16(smem_u32(s + 5120 + br * B_STR + bc),
                 B_g + (size_t)(k0 + br) * ND + col0 + bc);
        }
        cp_commit();
    };

    float acc[4][4][4] = {};
    issue(0, 0);

    #pragma unroll 1
    for (int it = 0; it < 32; it++) {
        const int buf = it & 1;
        if (it + 1 < 32) { issue(it + 1, buf ^ 1); cp_wait<1>(); }
        else             { cp_wait<0>(); }
        __syncthreads();
        __half* sA = smem + buf * STAGE_E;
        __half* sB = sA + 5120;
        #pragma unroll
        for (int kk = 0; kk < 2; kk++) {
            uint32_t aa[4][4], bb[4][2];
            #pragma unroll
            for (int i = 0; i < 4; i++) {
                int r = wm * 64 + i * 16 + laneRowA;
                int cA = kk * 16 + laneColA;
                ldsm_x4(aa[i], smem_u32(sA + r * A_STR + cA));
            }
            #pragma unroll
            for (int j = 0; j < 4; j++) {
                int rB = kk * 16 + laneB;
                int cB = wn * 32 + j * 8;
                ldsm_x2t(bb[j], smem_u32(sB + rB * B_STR + cB));
            }
            #pragma unroll
            for (int i = 0; i < 4; i++)
                #pragma unroll
                for (int j = 0; j < 4; j++)
                    mma_f16(acc[i][j], aa[i], bb[j][0], bb[j][1]);
        }
        __syncthreads();
    }

    // Epilogue
    #pragma unroll
    for (int i = 0; i < 4; i++) {
        int rbase = row0 + wm * 64 + i * 16 + (lane >> 2);
        #pragma unroll
        for (int j = 0; j < 4; j++) {
            int nb = col0 + wn * 32 + j * 8 + (lane & 3) * 2;
            #pragma unroll
            for (int e = 0; e < 4; e++) {
                int m = rbase + (e >> 1) * 8;
                int n = nb + (e & 1);
                float val = acc[i][j][e] + bias[n];
                if (EPI == 1) {
                    Cout[(size_t)m * Cc + n] = val;
                } else {
                    int b = m >> 11, t = m & 2047;
                    int which = n >> 10, rr = n & 1023;
                    int h = rr >> 6, d = rr & 63;
                    int bh_i = b * NH + h;
                    if (which == 0) {
                        __half vh_, vl_;
                        split_fp16(val * 0.125f, vh_, vl_);
                        size_t idx = ((size_t)bh_i * Tt + t) * HD + d;
                        g_qh[idx] = vh_; g_ql[idx] = vl_;
                    } else if (which == 1) {
                        size_t idx = ((size_t)bh_i * HD + d) * Tt + t;   // transposed
                        g_k[idx] = __float2half_rn(val);
                    } else {
                        size_t idx = ((size_t)bh_i * Tt + t) * HD + d;
                        g_v[idx] = __float2half_rn(val);
                    }
                }
            }
        }
    }
}

// ---------------------------------------------------------------------------
// Tensor-core causal flash attention (fp16 thin, as R9):
//   S  = Qh*K + Ql*K ; PV = P*V
// ---------------------------------------------------------------------------
#define FSTR 72
#define FSTAGE 9216

__global__ __launch_bounds__(128, 4) void flash_mma() {
    extern __shared__ __half fsm[];
    const int tid = threadIdx.x;
    const int w = tid >> 5, lane = tid & 31;
    const int qb = (int)gridDim.x - 1 - (int)blockIdx.x;
    const int bh = blockIdx.y;
    const int q0 = qb * 64;

    const __half* Qh_g = g_qh + (size_t)bh * Tt * HD;
    const __half* Ql_g = g_ql + (size_t)bh * Tt * HD;
    const __half* K_g  = g_k  + (size_t)bh * HD * Tt;
    const __half* V_g  = g_v  + (size_t)bh * Tt * HD;

    const int laneRowA = (lane & 7) + ((lane >> 3) & 1) * 8;
    const int laneColA = (lane >> 4) * 8;
    const int lb16 = lane & 15;
    const int lbc = (lane >> 4) * 8;

    {
        #pragma unroll
        for (int u = 0; u < 4; u++) {
            int idx = tid + u * 128;
            int r = idx >> 3, c = (idx & 7) * 8;
            cp16(smem_u32(fsm + r * FSTR + c), Qh_g + (size_t)(q0 + r) * HD + c);
            cp16(smem_u32(fsm + 4608 + r * FSTR + c), Ql_g + (size_t)(q0 + r) * HD + c);
        }
        cp_commit();
        cp_wait<0>();
        __syncthreads();
    }
    uint32_t qfh[4][4], qfl[4][4];
    #pragma unroll
    for (int kk = 0; kk < 4; kk++) {
        int r = w * 16 + laneRowA;
        int c = kk * 16 + laneColA;
        ldsm_x4(qfh[kk], smem_u32(fsm + r * FSTR + c));
        ldsm_x4(qfl[kk], smem_u32(fsm + 4608 + r * FSTR + c));
    }
    __syncthreads();

    auto issueKV = [&](int kt, int stage) {
        const int k0 = kt * 64;
        __half* s = fsm + stage * FSTAGE;
        #pragma unroll
        for (int u = 0; u < 4; u++) {
            int idx = tid + u * 128;
            int r = idx >> 3, c = (idx & 7) * 8;
            cp16(smem_u32(s + r * FSTR + c),        K_g + (size_t)r * Tt + k0 + c);
            cp16(smem_u32(s + 4608 + r * FSTR + c), V_g + (size_t)(k0 + r) * HD + c);
        }
        cp_commit();
    };

    float o[8][4] = {};
    float m0 = -1e30f, m1 = -1e30f, l0 = 0.f, l1 = 0.f;
    const int row0g = q0 + w * 16 + (lane >> 2);
    const int row1g = row0g + 8;

    issueKV(0, 0);

    #pragma unroll 1
    for (int kt = 0; kt <= qb; kt++) {
        const int buf = kt & 1;
        if (kt < qb) { issueKV(kt + 1, buf ^ 1); cp_wait<1>(); }
        else         { cp_wait<0>(); }
        __syncthreads();
        __half* sK = fsm + buf * FSTAGE;
        __half* sV = sK + 4608;

        float s[8][4] = {};
        #pragma unroll
        for (int kk = 0; kk < 4; kk++) {
            #pragma unroll
            for (int jp = 0; jp < 4; jp++) {
                uint32_t kb[4];
                ldsm_x4t(kb, smem_u32(sK + (kk * 16 + lb16) * FSTR + jp * 16 + lbc));
                #pragma unroll
                for (int h2 = 0; h2 < 2; h2++) {
                    int j = jp * 2 + h2;
                    mma_f16(s[j], qfh[kk], kb[2*h2], kb[2*h2+1]);
                    mma_f16(s[j], qfl[kk], kb[2*h2], kb[2*h2+1]);
                }
            }
        }

        if (kt == qb) {
            const int k0 = kt * 64;
            #pragma unroll
            for (int j = 0; j < 8; j++) {
                int colb = k0 + j * 8 + (lane & 3) * 2;
                if (colb > row0g)     s[j][0] = -1e30f;
                if (colb + 1 > row0g) s[j][1] = -1e30f;
                if (colb > row1g)     s[j][2] = -1e30f;
                if (colb + 1 > row1g) s[j][3] = -1e30f;
            }
        }

        float tmax0 = -1e30f, tmax1 = -1e30f;
        #pragma unroll
        for (int j = 0; j < 8; j++) {
            tmax0 = fmaxf(tmax0, fmaxf(s[j][0], s[j][1]));
            tmax1 = fmaxf(tmax1, fmaxf(s[j][2], s[j][3]));
        }
        tmax0 = fmaxf(tmax0, __shfl_xor_sync(0xffffffffu, tmax0, 1));
        tmax0 = fmaxf(tmax0, __shfl_xor_sync(0xffffffffu, tmax0, 2));
        tmax1 = fmaxf(tmax1, __shfl_xor_sync(0xffffffffu, tmax1, 1));
        tmax1 = fmaxf(tmax1, __shfl_xor_sync(0xffffffffu, tmax1, 2));
        float mn0 = fmaxf(m0, tmax0), mn1 = fmaxf(m1, tmax1);
        float al0 = __expf(m0 - mn0), al1 = __expf(m1 - mn1);
        m0 = mn0; m1 = mn1;
        float ps0 = 0.f, ps1 = 0.f;
        #pragma unroll
        for (int j = 0; j < 8; j++) {
            s[j][0] = __expf(s[j][0] - mn0);
            s[j][1] = __expf(s[j][1] - mn0);
            s[j][2] = __expf(s[j][2] - mn1);
            s[j][3] = __expf(s[j][3] - mn1);
            ps0 += s[j][0] + s[j][1];
            ps1 += s[j][2] + s[j][3];
        }
        l0 = l0 * al0 + ps0;
        l1 = l1 * al1 + ps1;
        #pragma unroll
        for (int j = 0; j < 8; j++) {
            o[j][0] *= al0; o[j][1] *= al0;
            o[j][2] *= al1; o[j][3] *= al1;
        }

        #pragma unroll
        for (int kk = 0; kk < 4; kk++) {
            uint32_t ap[4];
            ap[0] = pack_hf2(s[2*kk][0],   s[2*kk][1]);
            ap[1] = pack_hf2(s[2*kk][2],   s[2*kk][3]);
            ap[2] = pack_hf2(s[2*kk+1][0], s[2*kk+1][1]);
            ap[3] = pack_hf2(s[2*kk+1][2], s[2*kk+1][3]);
            #pragma unroll
            for (int jp = 0; jp < 4; jp++) {
                uint32_t vb[4];
                ldsm_x4t(vb, smem_u32(sV + (kk * 16 + lb16) * FSTR + jp * 16 + lbc));
                #pragma unroll
                for (int h2 = 0; h2 < 2; h2++) {
                    int j = jp * 2 + h2;
                    mma_f16(o[j], ap, vb[2*h2], vb[2*h2+1]);
                }
            }
        }
        __syncthreads();
    }

    l0 += __shfl_xor_sync(0xffffffffu, l0, 1);
    l0 += __shfl_xor_sync(0xffffffffu, l0, 2);
    l1 += __shfl_xor_sync(0xffffffffu, l1, 1);
    l1 += __shfl_xor_sync(0xffffffffu, l1, 2);
    float inv0 = 1.f / l0, inv1 = 1.f / l1;

    const int b = bh >> 4, h = bh & 15;
    #pragma unroll
    for (int j = 0; j < 8; j++) {
        int col = h * HD + j * 8 + (lane & 3) * 2;
        {
            size_t idx = ((size_t)(b * Tt + row0g)) * Cc + col;
            *reinterpret_cast<__half2*>(&g_att[idx]) =
                __floats2half2_rn(o[j][0] * inv0, o[j][1] * inv0);
        }
        {
            size_t idx = ((size_t)(b * Tt + row1g)) * Cc + col;
            *reinterpret_cast<__half2*>(&g_att[idx]) =
                __floats2half2_rn(o[j][2] * inv1, o[j][3] * inv1);
        }
    }
}

// ---------------------------------------------------------------------------
extern "C" void kernel_launch(void* const* d_in, const int* in_sizes, int n_in,
                              void* d_out, int out_size) {
    const float* x        = (const float*)d_in[0];
    const float* ln_scale = (const float*)d_in[2];
    const float* ln_bias  = (const float*)d_in[3];
    const float* qkv_w    = (const float*)d_in[4];
    const float* qkv_b    = (const float*)d_in[5];
    const float* proj_w   = (const float*)d_in[6];
    const float* proj_b   = (const float*)d_in[7];
    float* out = (float*)d_out;

    const int gemm_smem  = STAGE_E * 2 * (int)sizeof(__half);   // 37888
    const int flash_smem = FSTAGE * 2 * (int)sizeof(__half);    // 36864

    static bool attr_set = false;
    if (!attr_set) {
        cudaFuncSetAttribute(flash_mma,
                             cudaFuncAttributeMaxDynamicSharedMemorySize, flash_smem);
        cudaFuncSetAttribute(mma_gemm<QKV_N, 0>,
                             cudaFuncAttributeMaxDynamicSharedMemorySize, gemm_smem);
        cudaFuncSetAttribute(mma_gemm<Cc, 1>,
                             cudaFuncAttributeMaxDynamicSharedMemorySize, gemm_smem);
        attr_set = true;
    }

    __half *xn, *wq, *wp, *att;
    cudaGetSymbolAddress((void**)&xn, g_xn);
    cudaGetSymbolAddress((void**)&wq, g_wq);
    cudaGetSymbolAddress((void**)&wp, g_wp);
    cudaGetSymbolAddress((void**)&att, g_att);

    ln_kernel<<<MROWS, 256>>>(x, ln_scale, ln_bias);
    cvt_kernel<<<(Cc * QKV_N) / 1024, 256>>>(qkv_w, wq);
    cvt_kernel<<<(Cc * Cc) / 1024, 256>>>(proj_w, wp);

    mma_gemm<QKV_N, 0><<<dim3(QKV_N / 128, MROWS / 128), 256, gemm_smem>>>(
        xn, wq, qkv_b, nullptr);
    flash_mma<<<dim3(Tt / 64, Bb * NH), 128, flash_smem>>>();
    mma_gemm<Cc, 1><<<dim3(Cc / 128, MROWS / 128), 256, gemm_smem>>>(
        att, wp, proj_b, out);
}

// round 12
// speedup vs baseline: 7.4108x; 1.1665x over previous
#include <cuda_runtime.h>
#include <cuda_bf16.h>
#include <cuda_fp16.h>
#include <cstdint>
#include <math.h>

#define Bb 2
#define Tt 2048
#define Cc 1024
#define NH 16
#define HD 64
#define MROWS (Bb*Tt)          // 4096
#define QKV_N (3*Cc)           // 3072

// Scratch
__device__ __half g_xn  [MROWS*Cc];            // LN out single fp16
__device__ __half g_wq  [Cc*QKV_N];            // qkv W single fp16
__device__ __half g_wp  [Cc*Cc];               // proj W single fp16
__device__ __half g_q  [Bb*NH*Tt*HD];          // [b,h,t,d] single (scaled 1/8)
__device__ __half g_k  [Bb*NH*Tt*HD];          // [b,h,t,d] single
__device__ __half g_v  [Bb*NH*Tt*HD];          // [b,h,t,d] single
__device__ __half g_att[MROWS*Cc];             // attention out single fp16

__device__ __forceinline__ uint32_t smem_u32(const void* p) {
    return (uint32_t)__cvta_generic_to_shared(p);
}
__device__ __forceinline__ void cp16(uint32_t dst, const void* src) {
    asm volatile("cp.async.ca.shared.global [%0], [%1], 16;\n" :: "r"(dst), "l"(src));
}
__device__ __forceinline__ void cp_commit() { asm volatile("cp.async.commit_group;\n"); }
template<int N> __device__ __forceinline__ void cp_wait() {
    asm volatile("cp.async.wait_group %0;\n" :: "n"(N));
}
__device__ __forceinline__ void ldsm_x4(uint32_t a[4], uint32_t addr) {
    asm volatile("ldmatrix.sync.aligned.m8n8.x4.shared.b16 {%0,%1,%2,%3}, [%4];"
                 : "=r"(a[0]),"=r"(a[1]),"=r"(a[2]),"=r"(a[3]) : "r"(addr));
}
__device__ __forceinline__ void ldsm_x4t(uint32_t b[4], uint32_t addr) {
    asm volatile("ldmatrix.sync.aligned.m8n8.x4.trans.shared.b16 {%0,%1,%2,%3}, [%4];"
                 : "=r"(b[0]),"=r"(b[1]),"=r"(b[2]),"=r"(b[3]) : "r"(addr));
}
__device__ __forceinline__ void mma_f16(float c[4], const uint32_t a[4], const uint32_t b0, const uint32_t b1) {
    asm volatile("mma.sync.aligned.m16n8k16.row.col.f32.f16.f16.f32 "
        "{%0,%1,%2,%3}, {%4,%5,%6,%7}, {%8,%9}, {%0,%1,%2,%3};"
        : "+f"(c[0]),"+f"(c[1]),"+f"(c[2]),"+f"(c[3])
        : "r"(a[0]),"r"(a[1]),"r"(a[2]),"r"(a[3]), "r"(b0),"r"(b1));
}
__device__ __forceinline__ uint32_t pack_hf2(float x, float y) {
    __half2 t = __floats2half2_rn(x, y);
    return *reinterpret_cast<uint32_t*>(&t);
}

// ---------------------------------------------------------------------------
// LayerNorm -> single fp16
// ---------------------------------------------------------------------------
__device__ __forceinline__ float block_sum256(float v, float* red) {
    #pragma unroll
    for (int o = 16; o > 0; o >>= 1) v += __shfl_xor_sync(0xffffffffu, v, o);
    int w = threadIdx.x >> 5;
    if ((threadIdx.x & 31) == 0) red[w] = v;
    __syncthreads();
    float t = (threadIdx.x < 8) ? red[threadIdx.x] : 0.f;
    if (threadIdx.x < 32) {
        #pragma unroll
        for (int o = 4; o > 0; o >>= 1) t += __shfl_xor_sync(0xffffffffu, t, o);
        if (threadIdx.x == 0) red[0] = t;
    }
    __syncthreads();
    float r = red[0];
    __syncthreads();
    return r;
}

__global__ __launch_bounds__(256) void ln_kernel(
    const float* __restrict__ x, const float* __restrict__ scale,
    const float* __restrict__ bias) {
    __shared__ float red[8];
    const int row = blockIdx.x;
    const int tid = threadIdx.x;
    float4 v = reinterpret_cast<const float4*>(x + (size_t)row * Cc)[tid];
    float s = v.x + v.y + v.z + v.w;
    float mu = block_sum256(s, red) * (1.f / Cc);
    float dx = v.x - mu, dy = v.y - mu, dz = v.z - mu, dw = v.w - mu;
    float sq = dx*dx + dy*dy + dz*dz + dw*dw;
    float var = block_sum256(sq, red) * (1.f / Cc);
    float inv = rsqrtf(var + 1e-6f);
    float4 sc = reinterpret_cast<const float4*>(scale)[tid];
    float4 bi = reinterpret_cast<const float4*>(bias)[tid];
    size_t base = (size_t)row * Cc + tid * 4;
    *reinterpret_cast<__half2*>(&g_xn[base]) =
        __floats2half2_rn(dx * inv * sc.x + bi.x, dy * inv * sc.y + bi.y);
    *reinterpret_cast<__half2*>(&g_xn[base + 2]) =
        __floats2half2_rn(dz * inv * sc.z + bi.z, dw * inv * sc.w + bi.w);
}

// ---------------------------------------------------------------------------
// fp32 -> fp16 single (weights)
// ---------------------------------------------------------------------------
__global__ __launch_bounds__(256) void cvt_kernel(
    const float* __restrict__ src, __half* __restrict__ dst) {
    int i = (blockIdx.x * 256 + threadIdx.x) * 4;
    float4 v = *reinterpret_cast<const float4*>(src + i);
    *reinterpret_cast<__half2*>(&dst[i])     = __floats2half2_rn(v.x, v.y);
    *reinterpret_cast<__half2*>(&dst[i + 2]) = __floats2half2_rn(v.z, v.w);
}

// ---------------------------------------------------------------------------
// fp16 single tensor-core GEMM: 128x128 block, 8 warps (2x4), warp tile 64x32.
// B fragments via ldsm.x4t (2 per kk). Coalesced half2 epilogue stores.
// ---------------------------------------------------------------------------
#define STAGE_E 9472
#define A_STR 40
#define B_STR 136

template<int ND, int EPI>
__global__ __launch_bounds__(256, 2) void mma_gemm(
    const __half* __restrict__ A_g, const __half* __restrict__ B_g,
    const float* __restrict__ bias, float* __restrict__ Cout)
{
    extern __shared__ __half smem[];
    const int tid = threadIdx.x;
    const int wid = tid >> 5, lane = tid & 31;
    const int wm = wid >> 2, wn = wid & 3;
    const int row0 = blockIdx.y * 128;
    const int col0 = blockIdx.x * 128;

    const int laneRowA = (lane & 7) + ((lane >> 3) & 1) * 8;
    const int laneColA = (lane >> 4) * 8;
    const int lb16 = lane & 15;
    const int lbc = (lane >> 4) * 8;

    auto issue = [&](int it, int stage) {
        const int k0 = it * 32;
        __half* s = smem + stage * STAGE_E;
        #pragma unroll
        for (int u = 0; u < 2; u++) {
            int c = tid + u * 256;
            int ar = c >> 2, ac = (c & 3) * 8;
            cp16(smem_u32(s + ar * A_STR + ac),
                 A_g + (size_t)(row0 + ar) * Cc + k0 + ac);
            int br = c >> 4, bc = (c & 15) * 8;
            cp16(smem_u32(s + 5120 + br * B_STR + bc),
                 B_g + (size_t)(k0 + br) * ND + col0 + bc);
        }
        cp_commit();
    };

    float acc[4][4][4] = {};
    issue(0, 0);

    #pragma unroll 1
    for (int it = 0; it < 32; it++) {
        const int buf = it & 1;
        if (it + 1 < 32) { issue(it + 1, buf ^ 1); cp_wait<1>(); }
        else             { cp_wait<0>(); }
        __syncthreads();
        __half* sA = smem + buf * STAGE_E;
        __half* sB = sA + 5120;
        #pragma unroll
        for (int kk = 0; kk < 2; kk++) {
            uint32_t aa[4][4], bb[2][4];
            #pragma unroll
            for (int i = 0; i < 4; i++) {
                int r = wm * 64 + i * 16 + laneRowA;
                int cA = kk * 16 + laneColA;
                ldsm_x4(aa[i], smem_u32(sA + r * A_STR + cA));
            }
            #pragma unroll
            for (int jp = 0; jp < 2; jp++) {
                int rB = kk * 16 + lb16;
                int cB = wn * 32 + jp * 16 + lbc;
                ldsm_x4t(bb[jp], smem_u32(sB + rB * B_STR + cB));
            }
            #pragma unroll
            for (int i = 0; i < 4; i++)
                #pragma unroll
                for (int j = 0; j < 4; j++)
                    mma_f16(acc[i][j], aa[i], bb[j >> 1][(j & 1) * 2],
                            bb[j >> 1][(j & 1) * 2 + 1]);
        }
        __syncthreads();
    }

    // Epilogue: e pairs (0,1) at row rbase, (2,3) at row rbase+8; cols nb,nb+1.
    #pragma unroll
    for (int i = 0; i < 4; i++) {
        int rbase = row0 + wm * 64 + i * 16 + (lane >> 2);
        #pragma unroll
        for (int j = 0; j < 4; j++) {
            int nb = col0 + wn * 32 + j * 8 + (lane & 3) * 2;
            float v0 = acc[i][j][0] + bias[nb];
            float v1 = acc[i][j][1] + bias[nb + 1];
            float v2 = acc[i][j][2] + bias[nb];
            float v3 = acc[i][j][3] + bias[nb + 1];
            if (EPI == 1) {
                float2 p0 = {v0, v1}, p1 = {v2, v3};
                *reinterpret_cast<float2*>(&Cout[(size_t)rbase * Cc + nb]) = p0;
                *reinterpret_cast<float2*>(&Cout[(size_t)(rbase + 8) * Cc + nb]) = p1;
            } else {
                int b = rbase >> 11, t = rbase & 2047;
                int which = nb >> 10, rr = nb & 1023;
                int h = rr >> 6, d = rr & 63;
                float sc = (which == 0) ? 0.125f : 1.f;
                __half* dst = (which == 0) ? g_q : ((which == 1) ? g_k : g_v);
                size_t idx = (((size_t)(b * NH + h) * Tt) + t) * HD + d;
                *reinterpret_cast<__half2*>(&dst[idx]) =
                    __floats2half2_rn(v0 * sc, v1 * sc);
                *reinterpret_cast<__half2*>(&dst[idx + 8 * HD]) =
                    __floats2half2_rn(v2 * sc, v3 * sc);
            }
        }
    }
}

// ---------------------------------------------------------------------------
// Tensor-core causal flash attention, fully single fp16:
//   S  = Q*K^T  (K stored [t][d]; B frags via non-trans ldsm.x4)
//     ldsm.x4 matrix order: m0=(r0-7,c0-7) m1=(r8-15,c0-7) m2=(r0-7,c8-15)
//     m3=(r8-15,c8-15); B-operand pairs are (kb[0],kb[2]) and (kb[1],kb[3])
//     — same n-block, k and k+8.  (R11 bug: paired kb[0],kb[1].)
//   PV = P*V    (V via ldsm.x4t)
// ---------------------------------------------------------------------------
#define FSTR 72
#define FSTAGE 9216

__global__ __launch_bounds__(128, 4) void flash_mma() {
    extern __shared__ __half fsm[];
    const int tid = threadIdx.x;
    const int w = tid >> 5, lane = tid & 31;
    const int qb = (int)gridDim.x - 1 - (int)blockIdx.x;
    const int bh = blockIdx.y;
    const int q0 = qb * 64;

    const __half* Q_g = g_q + (size_t)bh * Tt * HD;
    const __half* K_g = g_k + (size_t)bh * Tt * HD;
    const __half* V_g = g_v + (size_t)bh * Tt * HD;

    const int laneRowA = (lane & 7) + ((lane >> 3) & 1) * 8;
    const int laneColA = (lane >> 4) * 8;
    const int lb16 = lane & 15;
    const int lbc = (lane >> 4) * 8;

    // stage Q through stage-0 smem, extract fragments
    {
        #pragma unroll
        for (int u = 0; u < 4; u++) {
            int idx = tid + u * 128;
            int r = idx >> 3, c = (idx & 7) * 8;
            cp16(smem_u32(fsm + r * FSTR + c), Q_g + (size_t)(q0 + r) * HD + c);
        }
        cp_commit();
        cp_wait<0>();
        __syncthreads();
    }
    uint32_t qf[4][4];
    #pragma unroll
    for (int kk = 0; kk < 4; kk++) {
        int r = w * 16 + laneRowA;
        int c = kk * 16 + laneColA;
        ldsm_x4(qf[kk], smem_u32(fsm + r * FSTR + c));
    }
    __syncthreads();

    auto issueKV = [&](int kt, int stage) {
        const int k0 = kt * 64;
        __half* s = fsm + stage * FSTAGE;
        #pragma unroll
        for (int u = 0; u < 4; u++) {
            int idx = tid + u * 128;
            int r = idx >> 3, c = (idx & 7) * 8;
            cp16(smem_u32(s + r * FSTR + c),        K_g + (size_t)(k0 + r) * HD + c);
            cp16(smem_u32(s + 4608 + r * FSTR + c), V_g + (size_t)(k0 + r) * HD + c);
        }
        cp_commit();
    };

    float o[8][4] = {};
    float m0 = -1e30f, m1 = -1e30f, l0 = 0.f, l1 = 0.f;
    const int row0g = q0 + w * 16 + (lane >> 2);
    const int row1g = row0g + 8;

    issueKV(0, 0);

    #pragma unroll 1
    for (int kt = 0; kt <= qb; kt++) {
        const int buf = kt & 1;
        if (kt < qb) { issueKV(kt + 1, buf ^ 1); cp_wait<1>(); }
        else         { cp_wait<0>(); }
        __syncthreads();
        __half* sK = fsm + buf * FSTAGE;
        __half* sV = sK + 4608;

        // ---- S = Q K^T. K rows = t (n-dim), cols = d (k-dim). ----
        float s[8][4] = {};
        #pragma unroll
        for (int kk = 0; kk < 4; kk++) {
            #pragma unroll
            for (int jp = 0; jp < 4; jp++) {
                uint32_t kb[4];
                int rT = jp * 16 + laneRowA;
                int cD = kk * 16 + laneColA;
                ldsm_x4(kb, smem_u32(sK + rT * FSTR + cD));
                mma_f16(s[jp * 2 + 0], qf[kk], kb[0], kb[2]);   // n-rows 0-7:  k, k+8
                mma_f16(s[jp * 2 + 1], qf[kk], kb[1], kb[3]);   // n-rows 8-15: k, k+8
            }
        }

        if (kt == qb) {
            const int k0 = kt * 64;
            #pragma unroll
            for (int j = 0; j < 8; j++) {
                int colb = k0 + j * 8 + (lane & 3) * 2;
                if (colb > row0g)     s[j][0] = -1e30f;
                if (colb + 1 > row0g) s[j][1] = -1e30f;
                if (colb > row1g)     s[j][2] = -1e30f;
                if (colb + 1 > row1g) s[j][3] = -1e30f;
            }
        }

        // ---- online softmax ----
        float tmax0 = -1e30f, tmax1 = -1e30f;
        #pragma unroll
        for (int j = 0; j < 8; j++) {
            tmax0 = fmaxf(tmax0, fmaxf(s[j][0], s[j][1]));
            tmax1 = fmaxf(tmax1, fmaxf(s[j][2], s[j][3]));
        }
        tmax0 = fmaxf(tmax0, __shfl_xor_sync(0xffffffffu, tmax0, 1));
        tmax0 = fmaxf(tmax0, __shfl_xor_sync(0xffffffffu, tmax0, 2));
        tmax1 = fmaxf(tmax1, __shfl_xor_sync(0xffffffffu, tmax1, 1));
        tmax1 = fmaxf(tmax1, __shfl_xor_sync(0xffffffffu, tmax1, 2));
        float mn0 = fmaxf(m0, tmax0), mn1 = fmaxf(m1, tmax1);
        float al0 = __expf(m0 - mn0), al1 = __expf(m1 - mn1);
        m0 = mn0; m1 = mn1;
        float ps0 = 0.f, ps1 = 0.f;
        #pragma unroll
        for (int j = 0; j < 8; j++) {
            s[j][0] = __expf(s[j][0] - mn0);
            s[j][1] = __expf(s[j][1] - mn0);
            s[j][2] = __expf(s[j][2] - mn1);
            s[j][3] = __expf(s[j][3] - mn1);
            ps0 += s[j][0] + s[j][1];
            ps1 += s[j][2] + s[j][3];
        }
        l0 = l0 * al0 + ps0;
        l1 = l1 * al1 + ps1;
        #pragma unroll
        for (int j = 0; j < 8; j++) {
            o[j][0] *= al0; o[j][1] *= al0;
            o[j][2] *= al1; o[j][3] *= al1;
        }

        // ---- O += P V ----
        #pragma unroll
        for (int kk = 0; kk < 4; kk++) {
            uint32_t ap[4];
            ap[0] = pack_hf2(s[2*kk][0],   s[2*kk][1]);
            ap[1] = pack_hf2(s[2*kk][2],   s[2*kk][3]);
            ap[2] = pack_hf2(s[2*kk+1][0], s[2*kk+1][1]);
            ap[3] = pack_hf2(s[2*kk+1][2], s[2*kk+1][3]);
            #pragma unroll
            for (int jp = 0; jp < 4; jp++) {
                uint32_t vb[4];
                ldsm_x4t(vb, smem_u32(sV + (kk * 16 + lb16) * FSTR + jp * 16 + lbc));
                mma_f16(o[jp * 2 + 0], ap, vb[0], vb[1]);
                mma_f16(o[jp * 2 + 1], ap, vb[2], vb[3]);
            }
        }
        __syncthreads();
    }

    l0 += __shfl_xor_sync(0xffffffffu, l0, 1);
    l0 += __shfl_xor_sync(0xffffffffu, l0, 2);
    l1 += __shfl_xor_sync(0xffffffffu, l1, 1);
    l1 += __shfl_xor_sync(0xffffffffu, l1, 2);
    float inv0 = 1.f / l0, inv1 = 1.f / l1;

    const int b = bh >> 4, h = bh & 15;
    #pragma unroll
    for (int j = 0; j < 8; j++) {
        int col = h * HD + j * 8 + (lane & 3) * 2;
        {
            size_t idx = ((size_t)(b * Tt + row0g)) * Cc + col;
            *reinterpret_cast<__half2*>(&g_att[idx]) =
                __floats2half2_rn(o[j][0] * inv0, o[j][1] * inv0);
        }
        {
            size_t idx = ((size_t)(b * Tt + row1g)) * Cc + col;
            *reinterpret_cast<__half2*>(&g_att[idx]) =
                __floats2half2_rn(o[j][2] * inv1, o[j][3] * inv1);
        }
    }
}

// ---------------------------------------------------------------------------
extern "C" void kernel_launch(void* const* d_in, const int* in_sizes, int n_in,
                              void* d_out, int out_size) {
    const float* x        = (const float*)d_in[0];
    const float* ln_scale = (const float*)d_in[2];
    const float* ln_bias  = (const float*)d_in[3];
    const float* qkv_w    = (const float*)d_in[4];
    const float* qkv_b    = (const float*)d_in[5];
    const float* proj_w   = (const float*)d_in[6];
    const float* proj_b   = (const float*)d_in[7];
    float* out = (float*)d_out;

    const int gemm_smem  = STAGE_E * 2 * (int)sizeof(__half);   // 37888
    const int flash_smem = FSTAGE * 2 * (int)sizeof(__half);    // 36864

    static bool attr_set = false;
    if (!attr_set) {
        cudaFuncSetAttribute(flash_mma,
                             cudaFuncAttributeMaxDynamicSharedMemorySize, flash_smem);
        cudaFuncSetAttribute(mma_gemm<QKV_N, 0>,
                             cudaFuncAttributeMaxDynamicSharedMemorySize, gemm_smem);
        cudaFuncSetAttribute(mma_gemm<Cc, 1>,
                             cudaFuncAttributeMaxDynamicSharedMemorySize, gemm_smem);
        attr_set = true;
    }

    __half *xn, *wq, *wp, *att;
    cudaGetSymbolAddress((void**)&xn, g_xn);
    cudaGetSymbolAddress((void**)&wq, g_wq);
    cudaGetSymbolAddress((void**)&wp, g_wp);
    cudaGetSymbolAddress((void**)&att, g_att);

    ln_kernel<<<MROWS, 256>>>(x, ln_scale, ln_bias);
    cvt_kernel<<<(Cc * QKV_N) / 1024, 256>>>(qkv_w, wq);
    cvt_kernel<<<(Cc * Cc) / 1024, 256>>>(proj_w, wp);

    mma_gemm<QKV_N, 0><<<dim3(QKV_N / 128, MROWS / 128), 256, gemm_smem>>>(
        xn, wq, qkv_b, nullptr);
    flash_mma<<<dim3(Tt / 64, Bb * NH), 128, flash_smem>>>();
    mma_gemm<Cc, 1><<<dim3(Cc / 128, MROWS / 128), 256, gemm_smem>>>(
        att, wp, proj_b, out);
}